// round 9
// baseline (speedup 1.0000x reference)
#include <cuda_runtime.h>
#include <cuda_bf16.h>
#include <math.h>

// ---------------- constants ----------------
#define BATCH   32
#define HDIM    2048
#define NHEADS  16
#define HEADD   128
#define DFF     8192
#define QKV_N   (3*HDIM)   // 6144
#define MAXS    2048
#define MAXBLK  32
#define PAGE    64
#define NUMBLK  1024
#define NSPLIT  32
#define CHUNK   64         // MAXS / NSPLIT == one KV page
#define TKC     32         // gemm k-chunk
#define TN      128        // gemm n-tile

// ---------------- scratch (no allocs allowed) ----------------
__device__ float g_x1 [BATCH*HDIM];
__device__ float g_qkv[BATCH*QKV_N];
__device__ float g_att[BATCH*HDIM];
__device__ float g_h  [BATCH*HDIM];
__device__ float g_x2 [BATCH*HDIM];
__device__ float g_ffn[BATCH*DFF];
__device__ float g_pm [BATCH*NHEADS*NSPLIT];
__device__ float g_ps [BATCH*NHEADS*NSPLIT];
__device__ float g_pa [BATCH*NHEADS*NSPLIT*HEADD];

// ---------------- helpers ----------------
__device__ __forceinline__ float gelu_exact(float x) {
    return 0.5f * x * (1.0f + erff(x * 0.70710678118654752f));
}

// A split: hi = rna-tf32(x), lo = x - hi (exact; HW truncates lo to tf32)
__device__ __forceinline__ void split_tf32(float x, unsigned &hi, unsigned &lo) {
    unsigned h;
    asm("cvt.rna.tf32.f32 %0, %1;" : "=r"(h) : "f"(x));
    hi = h;
    lo = __float_as_uint(x - __uint_as_float(h));
}
// W: single unbiased rounding to tf32
__device__ __forceinline__ unsigned rna_tf32(float x) {
    unsigned h;
    asm("cvt.rna.tf32.f32 %0, %1;" : "=r"(h) : "f"(x));
    return h;
}

__device__ __forceinline__ void mma_tf32(float d[4], const unsigned a[4],
                                         unsigned b0, unsigned b1) {
    asm volatile(
        "mma.sync.aligned.m16n8k8.row.col.f32.tf32.tf32.f32 "
        "{%0,%1,%2,%3}, {%4,%5,%6,%7}, {%8,%9}, {%0,%1,%2,%3};"
        : "+f"(d[0]), "+f"(d[1]), "+f"(d[2]), "+f"(d[3])
        : "r"(a[0]), "r"(a[1]), "r"(a[2]), "r"(a[3]), "r"(b0), "r"(b1));
}

// ---------------- LayerNorm: 32 rows x 2048 ----------------
__global__ void __launch_bounds__(256) ln_kernel(
    const float* __restrict__ x, const float* __restrict__ g,
    const float* __restrict__ b, float* __restrict__ y)
{
    int row = blockIdx.x;
    const float* xr = x + row * HDIM;
    float s = 0.f, s2 = 0.f;
    for (int i = threadIdx.x; i < HDIM; i += 256) {
        float v = xr[i]; s += v; s2 += v * v;
    }
    __shared__ float sh[16];
    int lane = threadIdx.x & 31, w = threadIdx.x >> 5;
    #pragma unroll
    for (int o = 16; o; o >>= 1) {
        s  += __shfl_xor_sync(0xffffffffu, s,  o);
        s2 += __shfl_xor_sync(0xffffffffu, s2, o);
    }
    if (lane == 0) { sh[w] = s; sh[8 + w] = s2; }
    __syncthreads();
    if (threadIdx.x == 0) {
        float S = 0.f, S2 = 0.f;
        #pragma unroll
        for (int i = 0; i < 8; i++) { S += sh[i]; S2 += sh[8 + i]; }
        sh[0] = S; sh[1] = S2;
    }
    __syncthreads();
    float mu  = sh[0] * (1.0f / HDIM);
    float var = sh[1] * (1.0f / HDIM) - mu * mu;
    float inv = rsqrtf(var + 1e-5f);
    float* yr = y + row * HDIM;
    for (int i = threadIdx.x; i < HDIM; i += 256)
        yr[i] = (xr[i] - mu) * inv * g[i] + b[i];
}

// ---------------- merged init: qkv=b, h=b+res, ffn=b ----------------
__global__ void __launch_bounds__(256) init3_kernel(
    float* __restrict__ qkv, const float* __restrict__ battn,
    float* __restrict__ h, const float* __restrict__ bproj,
    const float* __restrict__ hidden,
    float* __restrict__ ffn, const float* __restrict__ bfc)
{
    const int n1 = BATCH * QKV_N;
    const int n2 = n1 + BATCH * HDIM;
    const int n3 = n2 + BATCH * DFF;
    for (int i = blockIdx.x * 256 + threadIdx.x; i < n3; i += gridDim.x * 256) {
        if (i < n1) {
            qkv[i] = battn[i % QKV_N];
        } else if (i < n2) {
            int j = i - n1;
            h[j] = bproj[j & (HDIM - 1)] + hidden[j];
        } else {
            int j = i - n2;
            ffn[j] = bfc[j & (DFF - 1)];
        }
    }
}

// ---------------- fc2 prep: gelu(ffn) in place + out = h + b_fc2 ----------------
__global__ void __launch_bounds__(256) prep_fc2_kernel(
    float* __restrict__ ffn, float* __restrict__ out,
    const float* __restrict__ h, const float* __restrict__ bfc2)
{
    const int n1 = BATCH * DFF / 4;                 // gelu range (float4)
    const int n2 = n1 + BATCH * HDIM;               // out-init range (scalar)
    for (int i = blockIdx.x * 256 + threadIdx.x; i < n2; i += gridDim.x * 256) {
        if (i < n1) {
            float4 v = reinterpret_cast<float4*>(ffn)[i];
            v.x = gelu_exact(v.x); v.y = gelu_exact(v.y);
            v.z = gelu_exact(v.z); v.w = gelu_exact(v.w);
            reinterpret_cast<float4*>(ffn)[i] = v;
        } else {
            int j = i - n1;
            out[j] = h[j] + bfc2[j & (HDIM - 1)];
        }
    }
}

// ---------------- tensor-core GEMM: C[32,N] += A[32,K] @ W[K,N] ----------------
// 2xTF32. LDG.128->regs->STS.128 double-buffer (NOT cp.async: LDGSTS issue
// rate of 8 cyc/16B caps the chip at ~2.1 TB/s; LDG.128 path is ~25x fewer
// LSU slots). 2 CTAs/SM, static 44KB smem. split-K, atomicAdd into preinit C.
__global__ void __launch_bounds__(256, 2) gemm_tc(
    const float* __restrict__ A, const float* __restrict__ W,
    float* __restrict__ C, int K, int N)
{
    __shared__ __align__(16) float Ws[2][TKC][136];  // pad -> conflict-free frags
    __shared__ __align__(16) float As[2][32][36];

    int tid = threadIdx.x;
    int lane = tid & 31, warp = tid >> 5;
    int m0 = (warp & 1) * 16;
    int n0w = (warp >> 1) * 32;
    int nblk = blockIdx.x * TN;

    int kc = K / gridDim.y;
    int kbeg = blockIdx.y * kc;
    int nchunk = kc / TKC;

    float acc[4][4] = {};

    int am = tid >> 3, ak = (tid & 7) * 4;   // A coords (1 float4/thread)
    int gr = lane >> 2, kq = lane & 3;       // fragment coords

    // W coords: 4 float4 segments/thread; seg it: idx=it*256+tid
    int wk[4], wc[4];
    #pragma unroll
    for (int it = 0; it < 4; ++it) {
        int idx = it * 256 + tid;
        wk[it] = idx >> 5;
        wc[it] = (idx & 31) * 4;
    }

    float4 wr[4]; float4 ar;

    auto ldg_chunk = [&](int chunk) {
        int kb = kbeg + chunk * TKC;
        ar = *reinterpret_cast<const float4*>(&A[am * K + kb + ak]);
        #pragma unroll
        for (int it = 0; it < 4; ++it)
            wr[it] = *reinterpret_cast<const float4*>(
                &W[(size_t)(kb + wk[it]) * N + nblk + wc[it]]);
    };
    auto sts_chunk = [&](int s) {
        *reinterpret_cast<float4*>(&As[s][am][ak]) = ar;
        #pragma unroll
        for (int it = 0; it < 4; ++it)
            *reinterpret_cast<float4*>(&Ws[s][wk[it]][wc[it]]) = wr[it];
    };

    // prologue: chunk 0 to smem, chunk 1 staged in regs
    ldg_chunk(0);
    sts_chunk(0);
    if (nchunk > 1) ldg_chunk(1);
    __syncthreads();

    for (int i = 0; i < nchunk; ++i) {
        int s = i & 1;
        #pragma unroll
        for (int ks = 0; ks < 4; ++ks) {
            int k0 = ks * 8;
            unsigned ah[4], al[4];
            split_tf32(As[s][m0 + gr    ][k0 + kq    ], ah[0], al[0]);
            split_tf32(As[s][m0 + gr + 8][k0 + kq    ], ah[1], al[1]);
            split_tf32(As[s][m0 + gr    ][k0 + kq + 4], ah[2], al[2]);
            split_tf32(As[s][m0 + gr + 8][k0 + kq + 4], ah[3], al[3]);
            #pragma unroll
            for (int nt = 0; nt < 4; ++nt) {
                int nb2 = n0w + nt * 8 + gr;
                unsigned bh0 = rna_tf32(Ws[s][k0 + kq    ][nb2]);
                unsigned bh1 = rna_tf32(Ws[s][k0 + kq + 4][nb2]);
                mma_tf32(acc[nt], ah, bh0, bh1);
                mma_tf32(acc[nt], al, bh0, bh1);
            }
        }
        if (i + 1 < nchunk) {
            __syncthreads();            // all warps done compute(i): slot s^1 free
            sts_chunk(s ^ 1);           // stage chunk i+1
            if (i + 2 < nchunk) ldg_chunk(i + 2);   // start next LDG early
            __syncthreads();            // STS visible before compute(i+1)
        }
    }

    int cq = (lane & 3) * 2;
    #pragma unroll
    for (int nt = 0; nt < 4; ++nt) {
        int col = nblk + n0w + nt * 8 + cq;
        atomicAdd(&C[(m0 + gr    ) * N + col    ], acc[nt][0]);
        atomicAdd(&C[(m0 + gr    ) * N + col + 1], acc[nt][1]);
        atomicAdd(&C[(m0 + gr + 8) * N + col    ], acc[nt][2]);
        atomicAdd(&C[(m0 + gr + 8) * N + col + 1], acc[nt][3]);
    }
}

// ---------------- attention partial: one block per (b,h,page) ----------------
__global__ void __launch_bounds__(256) attn_partial(
    const float* __restrict__ qkv, const float* __restrict__ kv,
    const int* __restrict__ bt, const int* __restrict__ sl,
    float* __restrict__ pm, float* __restrict__ ps, float* __restrict__ pa)
{
    int b = blockIdx.x, h = blockIdx.y, sp = blockIdx.z;
    int tid = threadIdx.x, lane = tid & 31, w = tid >> 5;
    int pidx = (b * NHEADS + h) * NSPLIT + sp;
    int seq = sl[b];
    int t0 = sp * CHUNK;
    if (t0 >= seq) {
        if (tid == 0) { pm[pidx] = -INFINITY; ps[pidx] = 0.f; }
        return;
    }
    int nt = seq - t0; if (nt > CHUNK) nt = CHUNK;

    __shared__ float qs[HEADD];
    __shared__ float sc[CHUNK];
    __shared__ int   rbs;              // page base (float index, < 2^31)
    __shared__ float red[9];
    __shared__ float sa[2][HEADD];

    if (tid < HEADD) qs[tid] = qkv[b * QKV_N + h * HEADD + tid];
    if (tid == 0)
        rbs = bt[b * MAXBLK + sp] * (PAGE * NHEADS * HEADD) + h * HEADD;
    __syncthreads();
    int rb = rbs;

    const float scale = 0.08838834764831845f;  // 1/sqrt(128)
    float4 qx = reinterpret_cast<const float4*>(qs)[lane];

    // pass 1: scores. 4 tokens/warp/iter (loads clamped to page row 63 — always
    // resident; stores guarded by nt). Interleaved shfl chains pipeline.
    for (int tb = w * 4; tb < nt; tb += 32) {
        int u1 = min(tb + 1, 63), u2 = min(tb + 2, 63), u3 = min(tb + 3, 63);
        const float* base = kv + rb;
        float4 ka = reinterpret_cast<const float4*>(base + tb * (NHEADS * HEADD))[lane];
        float4 kb2 = reinterpret_cast<const float4*>(base + u1 * (NHEADS * HEADD))[lane];
        float4 kc2 = reinterpret_cast<const float4*>(base + u2 * (NHEADS * HEADD))[lane];
        float4 kd2 = reinterpret_cast<const float4*>(base + u3 * (NHEADS * HEADD))[lane];
        float d0 = ka.x  * qx.x + ka.y  * qx.y + ka.z  * qx.z + ka.w  * qx.w;
        float d1 = kb2.x * qx.x + kb2.y * qx.y + kb2.z * qx.z + kb2.w * qx.w;
        float d2 = kc2.x * qx.x + kc2.y * qx.y + kc2.z * qx.z + kc2.w * qx.w;
        float d3 = kd2.x * qx.x + kd2.y * qx.y + kd2.z * qx.z + kd2.w * qx.w;
        #pragma unroll
        for (int o = 16; o; o >>= 1) {
            d0 += __shfl_xor_sync(0xffffffffu, d0, o);
            d1 += __shfl_xor_sync(0xffffffffu, d1, o);
            d2 += __shfl_xor_sync(0xffffffffu, d2, o);
            d3 += __shfl_xor_sync(0xffffffffu, d3, o);
        }
        if (lane == 0) {
            sc[tb] = d0 * scale;
            if (tb + 1 < nt) sc[tb + 1] = d1 * scale;
            if (tb + 2 < nt) sc[tb + 2] = d2 * scale;
            if (tb + 3 < nt) sc[tb + 3] = d3 * scale;
        }
    }
    __syncthreads();

    // local max
    float m = -INFINITY;
    if (tid < nt) m = sc[tid];
    #pragma unroll
    for (int o = 16; o; o >>= 1) m = fmaxf(m, __shfl_xor_sync(0xffffffffu, m, o));
    if (lane == 0) red[w] = m;
    __syncthreads();
    if (tid == 0) {
        float mm = red[0];
        #pragma unroll
        for (int i = 1; i < 8; i++) mm = fmaxf(mm, red[i]);
        red[8] = mm;
    }
    __syncthreads();
    float M = red[8];
    __syncthreads();

    // exp + local sum
    float s = 0.f;
    if (tid < nt) {
        float e = __expf(sc[tid] - M);
        sc[tid] = e; s = e;
    }
    #pragma unroll
    for (int o = 16; o; o >>= 1) s += __shfl_xor_sync(0xffffffffu, s, o);
    if (lane == 0) red[w] = s;
    __syncthreads();
    if (tid == 0) {
        float S = 0.f;
        #pragma unroll
        for (int i = 0; i < 8; i++) S += red[i];
        pm[pidx] = M; ps[pidx] = S;
    }

    // pass 2: unnormalized weighted V. 2 halves x 4-way unroll.
    int d = tid & 127, half = tid >> 7;
    const float* Vb = kv + (size_t)NUMBLK * PAGE * NHEADS * HEADD;
    float a0 = 0.f, a1 = 0.f, a2 = 0.f, a3 = 0.f;
    int t = half;
    for (; t + 6 < nt; t += 8) {
        const float* v0 = Vb + rb + (t    ) * (NHEADS * HEADD);
        const float* v1 = Vb + rb + (t + 2) * (NHEADS * HEADD);
        const float* v2 = Vb + rb + (t + 4) * (NHEADS * HEADD);
        const float* v3 = Vb + rb + (t + 6) * (NHEADS * HEADD);
        a0 += sc[t    ] * v0[d];
        a1 += sc[t + 2] * v1[d];
        a2 += sc[t + 4] * v2[d];
        a3 += sc[t + 6] * v3[d];
    }
    for (; t < nt; t += 2) {
        const float* vr = Vb + rb + t * (NHEADS * HEADD);
        a0 += sc[t] * vr[d];
    }
    sa[half][d] = (a0 + a1) + (a2 + a3);
    __syncthreads();
    if (tid < HEADD) pa[(size_t)pidx * HEADD + tid] = sa[0][tid] + sa[1][tid];
}

// ---------------- attention combine: one block per (b,h) ----------------
__global__ void __launch_bounds__(128) attn_combine(
    const float* __restrict__ pm, const float* __restrict__ ps,
    const float* __restrict__ pa, float* __restrict__ out)
{
    int b = blockIdx.x, h = blockIdx.y;
    int idx = b * NHEADS + h;
    int tid = threadIdx.x;
    __shared__ float ms[NSPLIT], ss[NSPLIT];
    if (tid < NSPLIT) {
        ms[tid] = pm[idx * NSPLIT + tid];
        ss[tid] = ps[idx * NSPLIT + tid];
    }
    __syncthreads();
    float M = -INFINITY;
    #pragma unroll
    for (int i = 0; i < NSPLIT; i++)
        if (ss[i] > 0.f) M = fmaxf(M, ms[i]);
    float num = 0.f, den = 0.f;
    #pragma unroll
    for (int i = 0; i < NSPLIT; i++) {
        if (ss[i] > 0.f) {
            float wv = __expf(ms[i] - M);
            den += wv * ss[i];
            num += wv * pa[((size_t)idx * NSPLIT + i) * HEADD + tid];
        }
    }
    out[b * HDIM + h * HEADD + tid] = num / den;
}

// ---------------- host launcher ----------------
extern "C" void kernel_launch(void* const* d_in, const int* in_sizes, int n_in,
                              void* d_out, int out_size)
{
    const float* hidden = (const float*)d_in[0];
    const float* kv     = (const float*)d_in[1];
    const int*   bt     = (const int*)d_in[2];
    const int*   sl     = (const int*)d_in[3];
    int p = (n_in > 4 && in_sizes[4] == 1) ? 5 : 4;  // skip max_seq_len if present
    const float* ln1g  = (const float*)d_in[p + 0];
    const float* ln1b  = (const float*)d_in[p + 1];
    const float* ln2g  = (const float*)d_in[p + 2];
    const float* ln2b  = (const float*)d_in[p + 3];
    const float* wattn = (const float*)d_in[p + 4];
    const float* battn = (const float*)d_in[p + 5];
    const float* wproj = (const float*)d_in[p + 6];
    const float* bproj = (const float*)d_in[p + 7];
    const float* wfc   = (const float*)d_in[p + 8];
    const float* bfc   = (const float*)d_in[p + 9];
    const float* wfc2  = (const float*)d_in[p + 10];
    const float* bfc2  = (const float*)d_in[p + 11];
    float* out = (float*)d_out;

    float *x1, *qkvp, *att, *h, *x2, *ffn, *pm, *ps, *pa;
    cudaGetSymbolAddress((void**)&x1,   g_x1);
    cudaGetSymbolAddress((void**)&qkvp, g_qkv);
    cudaGetSymbolAddress((void**)&att,  g_att);
    cudaGetSymbolAddress((void**)&h,    g_h);
    cudaGetSymbolAddress((void**)&x2,   g_x2);
    cudaGetSymbolAddress((void**)&ffn,  g_ffn);
    cudaGetSymbolAddress((void**)&pm,   g_pm);
    cudaGetSymbolAddress((void**)&ps,   g_ps);
    cudaGetSymbolAddress((void**)&pa,   g_pa);

    // 1. ln1 + merged bias/residual inits
    ln_kernel<<<BATCH, 256>>>(hidden, ln1g, ln1b, x1);
    init3_kernel<<<512, 256>>>(qkvp, battn, h, bproj, hidden, ffn, bfc);
    // 2. qkv = x1 @ w_attn + b_attn   (48 x 8 = 384 blocks, kc=256)
    gemm_tc<<<dim3(QKV_N / TN, 8), 256>>>(x1, wattn, qkvp, HDIM, QKV_N);
    // 3. attention (flash-decode, 32-way page split)
    attn_partial<<<dim3(BATCH, NHEADS, NSPLIT), 256>>>(qkvp, kv, bt, sl, pm, ps, pa);
    attn_combine<<<dim3(BATCH, NHEADS), 128>>>(pm, ps, pa, att);
    // 4. h += attn @ w_proj   (16 x 16 = 256 blocks, kc=128)
    gemm_tc<<<dim3(HDIM / TN, 16), 256>>>(att, wproj, h, HDIM, HDIM);
    // 5. ln2
    ln_kernel<<<BATCH, 256>>>(h, ln2g, ln2b, x2);
    // 6. ffn += x2 @ w_fc   (64 x 8 = 512 blocks, kc=256)
    gemm_tc<<<dim3(DFF / TN, 8), 256>>>(x2, wfc, ffn, HDIM, DFF);
    // 6b. gelu(ffn) + out = h + b_fc2 (one kernel)
    prep_fc2_kernel<<<296, 256>>>(ffn, out, h, bfc2);
    // 7. out += gelu(ffn) @ w_fc2   (16 x 16 = 256 blocks, kc=512)
    gemm_tc<<<dim3(HDIM / TN, 16), 256>>>(ffn, wfc2, out, DFF, HDIM);
}

// round 10
// speedup vs baseline: 1.0798x; 1.0798x over previous
#include <cuda_runtime.h>
#include <cuda_bf16.h>
#include <math.h>

// ---------------- constants ----------------
#define BATCH   32
#define HDIM    2048
#define NHEADS  16
#define HEADD   128
#define DFF     8192
#define QKV_N   (3*HDIM)   // 6144
#define MAXS    2048
#define MAXBLK  32
#define PAGE    64
#define NUMBLK  1024
#define NSPLIT  32
#define CHUNK   64         // MAXS / NSPLIT == one KV page
#define TKC     32         // gemm k-chunk
#define TN      128        // gemm n-tile
#define NSTAGE  4          // gemm pipeline stages

// ---------------- scratch (no allocs allowed) ----------------
__device__ float g_x1 [BATCH*HDIM];
__device__ float g_qkv[BATCH*QKV_N];
__device__ float g_att[BATCH*HDIM];
__device__ float g_h  [BATCH*HDIM];
__device__ float g_x2 [BATCH*HDIM];
__device__ float g_ffn[BATCH*DFF];
__device__ float g_pm [BATCH*NHEADS*NSPLIT];
__device__ float g_ps [BATCH*NHEADS*NSPLIT];
__device__ float g_pa [BATCH*NHEADS*NSPLIT*HEADD];

// ---------------- helpers ----------------
__device__ __forceinline__ float gelu_exact(float x) {
    return 0.5f * x * (1.0f + erff(x * 0.70710678118654752f));
}

// single unbiased rounding to tf32 (1xTF32 path)
__device__ __forceinline__ unsigned rna_tf32(float x) {
    unsigned h;
    asm("cvt.rna.tf32.f32 %0, %1;" : "=r"(h) : "f"(x));
    return h;
}

__device__ __forceinline__ void mma_tf32(float d[4], const unsigned a[4],
                                         unsigned b0, unsigned b1) {
    asm volatile(
        "mma.sync.aligned.m16n8k8.row.col.f32.tf32.tf32.f32 "
        "{%0,%1,%2,%3}, {%4,%5,%6,%7}, {%8,%9}, {%0,%1,%2,%3};"
        : "+f"(d[0]), "+f"(d[1]), "+f"(d[2]), "+f"(d[3])
        : "r"(a[0]), "r"(a[1]), "r"(a[2]), "r"(a[3]), "r"(b0), "r"(b1));
}

__device__ __forceinline__ void cp_async16(void* smem, const void* g) {
    unsigned s = (unsigned)__cvta_generic_to_shared(smem);
    asm volatile("cp.async.cg.shared.global [%0], [%1], 16;" :: "r"(s), "l"(g));
}
__device__ __forceinline__ void cp_commit() {
    asm volatile("cp.async.commit_group;");
}
template<int N>
__device__ __forceinline__ void cp_wait() {
    asm volatile("cp.async.wait_group %0;" :: "n"(N));
}

// ---------------- LayerNorm: 32 rows x 2048 ----------------
__global__ void __launch_bounds__(256) ln_kernel(
    const float* __restrict__ x, const float* __restrict__ g,
    const float* __restrict__ b, float* __restrict__ y)
{
    int row = blockIdx.x;
    const float* xr = x + row * HDIM;
    float s = 0.f, s2 = 0.f;
    for (int i = threadIdx.x; i < HDIM; i += 256) {
        float v = xr[i]; s += v; s2 += v * v;
    }
    __shared__ float sh[16];
    int lane = threadIdx.x & 31, w = threadIdx.x >> 5;
    #pragma unroll
    for (int o = 16; o; o >>= 1) {
        s  += __shfl_xor_sync(0xffffffffu, s,  o);
        s2 += __shfl_xor_sync(0xffffffffu, s2, o);
    }
    if (lane == 0) { sh[w] = s; sh[8 + w] = s2; }
    __syncthreads();
    if (threadIdx.x == 0) {
        float S = 0.f, S2 = 0.f;
        #pragma unroll
        for (int i = 0; i < 8; i++) { S += sh[i]; S2 += sh[8 + i]; }
        sh[0] = S; sh[1] = S2;
    }
    __syncthreads();
    float mu  = sh[0] * (1.0f / HDIM);
    float var = sh[1] * (1.0f / HDIM) - mu * mu;
    float inv = rsqrtf(var + 1e-5f);
    float* yr = y + row * HDIM;
    for (int i = threadIdx.x; i < HDIM; i += 256)
        yr[i] = (xr[i] - mu) * inv * g[i] + b[i];
}

// ---------------- merged init: qkv=b, h=b+res, ffn=b ----------------
__global__ void __launch_bounds__(256) init3_kernel(
    float* __restrict__ qkv, const float* __restrict__ battn,
    float* __restrict__ h, const float* __restrict__ bproj,
    const float* __restrict__ hidden,
    float* __restrict__ ffn, const float* __restrict__ bfc)
{
    const int n1 = BATCH * QKV_N;
    const int n2 = n1 + BATCH * HDIM;
    const int n3 = n2 + BATCH * DFF;
    for (int i = blockIdx.x * 256 + threadIdx.x; i < n3; i += gridDim.x * 256) {
        if (i < n1) {
            qkv[i] = battn[i % QKV_N];
        } else if (i < n2) {
            int j = i - n1;
            h[j] = bproj[j & (HDIM - 1)] + hidden[j];
        } else {
            int j = i - n2;
            ffn[j] = bfc[j & (DFF - 1)];
        }
    }
}

// ---------------- fc2 prep: gelu(ffn) in place + out = h + b_fc2 ----------------
__global__ void __launch_bounds__(256) prep_fc2_kernel(
    float* __restrict__ ffn, float* __restrict__ out,
    const float* __restrict__ h, const float* __restrict__ bfc2)
{
    const int n1 = BATCH * DFF / 4;                 // gelu range (float4)
    const int n2 = n1 + BATCH * HDIM;               // out-init range (scalar)
    for (int i = blockIdx.x * 256 + threadIdx.x; i < n2; i += gridDim.x * 256) {
        if (i < n1) {
            float4 v = reinterpret_cast<float4*>(ffn)[i];
            v.x = gelu_exact(v.x); v.y = gelu_exact(v.y);
            v.z = gelu_exact(v.z); v.w = gelu_exact(v.w);
            reinterpret_cast<float4*>(ffn)[i] = v;
        } else {
            int j = i - n1;
            out[j] = h[j] + bfc2[j & (HDIM - 1)];
        }
    }
}

// ---------------- tensor-core GEMM: C[32,N] += A[32,K] @ W[K,N] ----------------
// 1xTF32 (A and W each rounded once with rna — unbiased). Halves MMA count vs
// 2xTF32; the GEMM stack measured MMA-rt-bound, so this is the binding lever.
// 4-stage cp.async ring, 2 CTAs/SM, ONE barrier per chunk.
// split-K via gridDim.y, atomicAdd into bias-preinitialized C.
#define WS_FL (TKC*136)
#define AS_FL (32*36)
#define GEMM_SMEM (NSTAGE*(WS_FL+AS_FL)*4)
__global__ void __launch_bounds__(256, 2) gemm_tc(
    const float* __restrict__ A, const float* __restrict__ W,
    float* __restrict__ C, int K, int N)
{
    extern __shared__ float smp[];
    float (*Ws)[TKC][136] = reinterpret_cast<float(*)[TKC][136]>(smp);
    float (*As)[32][36]   = reinterpret_cast<float(*)[32][36]>(smp + NSTAGE * WS_FL);

    int tid = threadIdx.x;
    int lane = tid & 31, warp = tid >> 5;
    int m0 = (warp & 1) * 16;
    int n0w = (warp >> 1) * 32;
    int nblk = blockIdx.x * TN;

    int kc = K / gridDim.y;
    int kbeg = blockIdx.y * kc;
    int nchunk = kc / TKC;

    float acc[4][4] = {};

    int am = tid >> 3, ak = (tid & 7) * 4;   // A staging coords (1 seg/thread)
    int gr = lane >> 2, kq = lane & 3;       // fragment coords

    auto prefetch = [&](int chunk) {
        int kb = kbeg + chunk * TKC;
        int s = chunk & (NSTAGE - 1);
        cp_async16(&As[s][am][ak], &A[am * K + kb + ak]);
        #pragma unroll
        for (int it = 0; it < 4; ++it) {
            int idx = it * 256 + tid;
            int kk = idx >> 5, c4 = (idx & 31) * 4;
            cp_async16(&Ws[s][kk][c4], &W[(size_t)(kb + kk) * N + nblk + c4]);
        }
    };

    #pragma unroll
    for (int c = 0; c < NSTAGE - 1; ++c) {
        if (c < nchunk) prefetch(c);
        cp_commit();
    }

    for (int i = 0; i < nchunk; ++i) {
        cp_wait<NSTAGE - 2>();    // group i complete
        __syncthreads();          // all warps done with compute(i-1) and see stage i
        if (i + NSTAGE - 1 < nchunk) prefetch(i + NSTAGE - 1);
        cp_commit();
        int s = i & (NSTAGE - 1);
        #pragma unroll
        for (int ks = 0; ks < 4; ++ks) {
            int k0 = ks * 8;
            unsigned ah[4];
            ah[0] = rna_tf32(As[s][m0 + gr    ][k0 + kq    ]);
            ah[1] = rna_tf32(As[s][m0 + gr + 8][k0 + kq    ]);
            ah[2] = rna_tf32(As[s][m0 + gr    ][k0 + kq + 4]);
            ah[3] = rna_tf32(As[s][m0 + gr + 8][k0 + kq + 4]);
            #pragma unroll
            for (int nt = 0; nt < 4; ++nt) {
                int nb2 = n0w + nt * 8 + gr;
                unsigned bh0 = rna_tf32(Ws[s][k0 + kq    ][nb2]);
                unsigned bh1 = rna_tf32(Ws[s][k0 + kq + 4][nb2]);
                mma_tf32(acc[nt], ah, bh0, bh1);
            }
        }
    }

    int cq = (lane & 3) * 2;
    #pragma unroll
    for (int nt = 0; nt < 4; ++nt) {
        int col = nblk + n0w + nt * 8 + cq;
        atomicAdd(&C[(m0 + gr    ) * N + col    ], acc[nt][0]);
        atomicAdd(&C[(m0 + gr    ) * N + col + 1], acc[nt][1]);
        atomicAdd(&C[(m0 + gr + 8) * N + col    ], acc[nt][2]);
        atomicAdd(&C[(m0 + gr + 8) * N + col + 1], acc[nt][3]);
    }
}

// ---------------- attention partial: one block per (b,h,page) ----------------
__global__ void __launch_bounds__(256) attn_partial(
    const float* __restrict__ qkv, const float* __restrict__ kv,
    const int* __restrict__ bt, const int* __restrict__ sl,
    float* __restrict__ pm, float* __restrict__ ps, float* __restrict__ pa)
{
    int b = blockIdx.x, h = blockIdx.y, sp = blockIdx.z;
    int tid = threadIdx.x, lane = tid & 31, w = tid >> 5;
    int pidx = (b * NHEADS + h) * NSPLIT + sp;
    int seq = sl[b];
    int t0 = sp * CHUNK;
    if (t0 >= seq) {
        if (tid == 0) { pm[pidx] = -INFINITY; ps[pidx] = 0.f; }
        return;
    }
    int nt = seq - t0; if (nt > CHUNK) nt = CHUNK;

    __shared__ float qs[HEADD];
    __shared__ float sc[CHUNK];
    __shared__ int   rbs;              // page base (float index, < 2^31)
    __shared__ float red[9];
    __shared__ float sa[2][HEADD];

    if (tid < HEADD) qs[tid] = qkv[b * QKV_N + h * HEADD + tid];
    if (tid == 0)
        rbs = bt[b * MAXBLK + sp] * (PAGE * NHEADS * HEADD) + h * HEADD;
    __syncthreads();
    int rb = rbs;

    const float scale = 0.08838834764831845f;  // 1/sqrt(128)
    float4 qx = reinterpret_cast<const float4*>(qs)[lane];

    // pass 1: scores. 4 tokens/warp/iter (loads clamped to page row 63 — always
    // resident; stores guarded by nt). Interleaved shfl chains pipeline.
    for (int tb = w * 4; tb < nt; tb += 32) {
        int u1 = min(tb + 1, 63), u2 = min(tb + 2, 63), u3 = min(tb + 3, 63);
        const float* base = kv + rb;
        float4 ka = reinterpret_cast<const float4*>(base + tb * (NHEADS * HEADD))[lane];
        float4 kb2 = reinterpret_cast<const float4*>(base + u1 * (NHEADS * HEADD))[lane];
        float4 kc2 = reinterpret_cast<const float4*>(base + u2 * (NHEADS * HEADD))[lane];
        float4 kd2 = reinterpret_cast<const float4*>(base + u3 * (NHEADS * HEADD))[lane];
        float d0 = ka.x  * qx.x + ka.y  * qx.y + ka.z  * qx.z + ka.w  * qx.w;
        float d1 = kb2.x * qx.x + kb2.y * qx.y + kb2.z * qx.z + kb2.w * qx.w;
        float d2 = kc2.x * qx.x + kc2.y * qx.y + kc2.z * qx.z + kc2.w * qx.w;
        float d3 = kd2.x * qx.x + kd2.y * qx.y + kd2.z * qx.z + kd2.w * qx.w;
        #pragma unroll
        for (int o = 16; o; o >>= 1) {
            d0 += __shfl_xor_sync(0xffffffffu, d0, o);
            d1 += __shfl_xor_sync(0xffffffffu, d1, o);
            d2 += __shfl_xor_sync(0xffffffffu, d2, o);
            d3 += __shfl_xor_sync(0xffffffffu, d3, o);
        }
        if (lane == 0) {
            sc[tb] = d0 * scale;
            if (tb + 1 < nt) sc[tb + 1] = d1 * scale;
            if (tb + 2 < nt) sc[tb + 2] = d2 * scale;
            if (tb + 3 < nt) sc[tb + 3] = d3 * scale;
        }
    }
    __syncthreads();

    // local max
    float m = -INFINITY;
    if (tid < nt) m = sc[tid];
    #pragma unroll
    for (int o = 16; o; o >>= 1) m = fmaxf(m, __shfl_xor_sync(0xffffffffu, m, o));
    if (lane == 0) red[w] = m;
    __syncthreads();
    if (tid == 0) {
        float mm = red[0];
        #pragma unroll
        for (int i = 1; i < 8; i++) mm = fmaxf(mm, red[i]);
        red[8] = mm;
    }
    __syncthreads();
    float M = red[8];
    __syncthreads();

    // exp + local sum
    float s = 0.f;
    if (tid < nt) {
        float e = __expf(sc[tid] - M);
        sc[tid] = e; s = e;
    }
    #pragma unroll
    for (int o = 16; o; o >>= 1) s += __shfl_xor_sync(0xffffffffu, s, o);
    if (lane == 0) red[w] = s;
    __syncthreads();
    if (tid == 0) {
        float S = 0.f;
        #pragma unroll
        for (int i = 0; i < 8; i++) S += red[i];
        pm[pidx] = M; ps[pidx] = S;
    }

    // pass 2: unnormalized weighted V. 2 halves x 4-way unroll.
    int d = tid & 127, half = tid >> 7;
    const float* Vb = kv + (size_t)NUMBLK * PAGE * NHEADS * HEADD;
    float a0 = 0.f, a1 = 0.f, a2 = 0.f, a3 = 0.f;
    int t = half;
    for (; t + 6 < nt; t += 8) {
        const float* v0 = Vb + rb + (t    ) * (NHEADS * HEADD);
        const float* v1 = Vb + rb + (t + 2) * (NHEADS * HEADD);
        const float* v2 = Vb + rb + (t + 4) * (NHEADS * HEADD);
        const float* v3 = Vb + rb + (t + 6) * (NHEADS * HEADD);
        a0 += sc[t    ] * v0[d];
        a1 += sc[t + 2] * v1[d];
        a2 += sc[t + 4] * v2[d];
        a3 += sc[t + 6] * v3[d];
    }
    for (; t < nt; t += 2) {
        const float* vr = Vb + rb + t * (NHEADS * HEADD);
        a0 += sc[t] * vr[d];
    }
    sa[half][d] = (a0 + a1) + (a2 + a3);
    __syncthreads();
    if (tid < HEADD) pa[(size_t)pidx * HEADD + tid] = sa[0][tid] + sa[1][tid];
}

// ---------------- attention combine: one block per (b,h) ----------------
__global__ void __launch_bounds__(128) attn_combine(
    const float* __restrict__ pm, const float* __restrict__ ps,
    const float* __restrict__ pa, float* __restrict__ out)
{
    int b = blockIdx.x, h = blockIdx.y;
    int idx = b * NHEADS + h;
    int tid = threadIdx.x;
    __shared__ float ms[NSPLIT], ss[NSPLIT];
    if (tid < NSPLIT) {
        ms[tid] = pm[idx * NSPLIT + tid];
        ss[tid] = ps[idx * NSPLIT + tid];
    }
    __syncthreads();
    float M = -INFINITY;
    #pragma unroll
    for (int i = 0; i < NSPLIT; i++)
        if (ss[i] > 0.f) M = fmaxf(M, ms[i]);
    float num = 0.f, den = 0.f;
    #pragma unroll
    for (int i = 0; i < NSPLIT; i++) {
        if (ss[i] > 0.f) {
            float wv = __expf(ms[i] - M);
            den += wv * ss[i];
            num += wv * pa[((size_t)idx * NSPLIT + i) * HEADD + tid];
        }
    }
    out[b * HDIM + h * HEADD + tid] = num / den;
}

// ---------------- host launcher ----------------
extern "C" void kernel_launch(void* const* d_in, const int* in_sizes, int n_in,
                              void* d_out, int out_size)
{
    const float* hidden = (const float*)d_in[0];
    const float* kv     = (const float*)d_in[1];
    const int*   bt     = (const int*)d_in[2];
    const int*   sl     = (const int*)d_in[3];
    int p = (n_in > 4 && in_sizes[4] == 1) ? 5 : 4;  // skip max_seq_len if present
    const float* ln1g  = (const float*)d_in[p + 0];
    const float* ln1b  = (const float*)d_in[p + 1];
    const float* ln2g  = (const float*)d_in[p + 2];
    const float* ln2b  = (const float*)d_in[p + 3];
    const float* wattn = (const float*)d_in[p + 4];
    const float* battn = (const float*)d_in[p + 5];
    const float* wproj = (const float*)d_in[p + 6];
    const float* bproj = (const float*)d_in[p + 7];
    const float* wfc   = (const float*)d_in[p + 8];
    const float* bfc   = (const float*)d_in[p + 9];
    const float* wfc2  = (const float*)d_in[p + 10];
    const float* bfc2  = (const float*)d_in[p + 11];
    float* out = (float*)d_out;

    float *x1, *qkvp, *att, *h, *x2, *ffn, *pm, *ps, *pa;
    cudaGetSymbolAddress((void**)&x1,   g_x1);
    cudaGetSymbolAddress((void**)&qkvp, g_qkv);
    cudaGetSymbolAddress((void**)&att,  g_att);
    cudaGetSymbolAddress((void**)&h,    g_h);
    cudaGetSymbolAddress((void**)&x2,   g_x2);
    cudaGetSymbolAddress((void**)&ffn,  g_ffn);
    cudaGetSymbolAddress((void**)&pm,   g_pm);
    cudaGetSymbolAddress((void**)&ps,   g_ps);
    cudaGetSymbolAddress((void**)&pa,   g_pa);

    cudaFuncSetAttribute(gemm_tc,
        cudaFuncAttributeMaxDynamicSharedMemorySize, GEMM_SMEM);

    // 1. ln1 + merged bias/residual inits
    ln_kernel<<<BATCH, 256>>>(hidden, ln1g, ln1b, x1);
    init3_kernel<<<512, 256>>>(qkvp, battn, h, bproj, hidden, ffn, bfc);
    // 2. qkv = x1 @ w_attn + b_attn   (48 x 8 = 384 blocks, kc=256)
    gemm_tc<<<dim3(QKV_N / TN, 8), 256, GEMM_SMEM>>>(x1, wattn, qkvp, HDIM, QKV_N);
    // 3. attention (flash-decode, 32-way page split)
    attn_partial<<<dim3(BATCH, NHEADS, NSPLIT), 256>>>(qkvp, kv, bt, sl, pm, ps, pa);
    attn_combine<<<dim3(BATCH, NHEADS), 128>>>(pm, ps, pa, att);
    // 4. h += attn @ w_proj   (16 x 16 = 256 blocks, kc=128)
    gemm_tc<<<dim3(HDIM / TN, 16), 256, GEMM_SMEM>>>(att, wproj, h, HDIM, HDIM);
    // 5. ln2
    ln_kernel<<<BATCH, 256>>>(h, ln2g, ln2b, x2);
    // 6. ffn += x2 @ w_fc   (64 x 8 = 512 blocks, kc=256)
    gemm_tc<<<dim3(DFF / TN, 8), 256, GEMM_SMEM>>>(x2, wfc, ffn, HDIM, DFF);
    // 6b. gelu(ffn) + out = h + b_fc2 (one kernel)
    prep_fc2_kernel<<<296, 256>>>(ffn, out, h, bfc2);
    // 7. out += gelu(ffn) @ w_fc2   (16 x 16 = 256 blocks, kc=512)
    gemm_tc<<<dim3(HDIM / TN, 16), 256, GEMM_SMEM>>>(ffn, wfc2, out, DFF, HDIM);
}

// round 11
// speedup vs baseline: 1.1190x; 1.0363x over previous
#include <cuda_runtime.h>
#include <cuda_bf16.h>
#include <math.h>

// ---------------- constants ----------------
#define BATCH   32
#define HDIM    2048
#define NHEADS  16
#define HEADD   128
#define DFF     8192
#define QKV_N   (3*HDIM)   // 6144
#define MAXS    2048
#define MAXBLK  32
#define PAGE    64
#define NUMBLK  1024
#define NSPLIT  32
#define CHUNK   64         // MAXS / NSPLIT == one KV page
#define TKC     32         // gemm k-chunk
#define TN      128        // gemm n-tile
#define NSTAGE  3          // gemm pipeline stages

// ---------------- scratch (no allocs allowed) ----------------
__device__ float g_x1 [BATCH*HDIM];
__device__ float g_qkv[BATCH*QKV_N];
__device__ float g_att[BATCH*HDIM];
__device__ float g_h  [BATCH*HDIM];
__device__ float g_x2 [BATCH*HDIM];
__device__ float g_ffn[BATCH*DFF];
__device__ float g_pm [BATCH*NHEADS*NSPLIT];
__device__ float g_ps [BATCH*NHEADS*NSPLIT];
__device__ float g_pa [BATCH*NHEADS*NSPLIT*HEADD];

// ---------------- helpers ----------------
__device__ __forceinline__ float gelu_exact(float x) {
    return 0.5f * x * (1.0f + erff(x * 0.70710678118654752f));
}

// unbiased rounding to tf32 (used for A only; W is fed raw — HW truncates)
__device__ __forceinline__ unsigned rna_tf32(float x) {
    unsigned h;
    asm("cvt.rna.tf32.f32 %0, %1;" : "=r"(h) : "f"(x));
    return h;
}

__device__ __forceinline__ void mma_tf32(float d[4], const unsigned a[4],
                                         unsigned b0, unsigned b1) {
    asm volatile(
        "mma.sync.aligned.m16n8k8.row.col.f32.tf32.tf32.f32 "
        "{%0,%1,%2,%3}, {%4,%5,%6,%7}, {%8,%9}, {%0,%1,%2,%3};"
        : "+f"(d[0]), "+f"(d[1]), "+f"(d[2]), "+f"(d[3])
        : "r"(a[0]), "r"(a[1]), "r"(a[2]), "r"(a[3]), "r"(b0), "r"(b1));
}

__device__ __forceinline__ void cp_async16(void* smem, const void* g) {
    unsigned s = (unsigned)__cvta_generic_to_shared(smem);
    asm volatile("cp.async.cg.shared.global [%0], [%1], 16;" :: "r"(s), "l"(g));
}
__device__ __forceinline__ void cp_commit() {
    asm volatile("cp.async.commit_group;");
}
template<int N>
__device__ __forceinline__ void cp_wait() {
    asm volatile("cp.async.wait_group %0;" :: "n"(N));
}

// ---------------- LayerNorm: 32 rows x 2048 ----------------
__global__ void __launch_bounds__(256) ln_kernel(
    const float* __restrict__ x, const float* __restrict__ g,
    const float* __restrict__ b, float* __restrict__ y)
{
    int row = blockIdx.x;
    const float* xr = x + row * HDIM;
    float s = 0.f, s2 = 0.f;
    for (int i = threadIdx.x; i < HDIM; i += 256) {
        float v = xr[i]; s += v; s2 += v * v;
    }
    __shared__ float sh[16];
    int lane = threadIdx.x & 31, w = threadIdx.x >> 5;
    #pragma unroll
    for (int o = 16; o; o >>= 1) {
        s  += __shfl_xor_sync(0xffffffffu, s,  o);
        s2 += __shfl_xor_sync(0xffffffffu, s2, o);
    }
    if (lane == 0) { sh[w] = s; sh[8 + w] = s2; }
    __syncthreads();
    if (threadIdx.x == 0) {
        float S = 0.f, S2 = 0.f;
        #pragma unroll
        for (int i = 0; i < 8; i++) { S += sh[i]; S2 += sh[8 + i]; }
        sh[0] = S; sh[1] = S2;
    }
    __syncthreads();
    float mu  = sh[0] * (1.0f / HDIM);
    float var = sh[1] * (1.0f / HDIM) - mu * mu;
    float inv = rsqrtf(var + 1e-5f);
    float* yr = y + row * HDIM;
    for (int i = threadIdx.x; i < HDIM; i += 256)
        yr[i] = (xr[i] - mu) * inv * g[i] + b[i];
}

// ---------------- merged init: qkv=b, h=b+res, ffn=b ----------------
__global__ void __launch_bounds__(256) init3_kernel(
    float* __restrict__ qkv, const float* __restrict__ battn,
    float* __restrict__ h, const float* __restrict__ bproj,
    const float* __restrict__ hidden,
    float* __restrict__ ffn, const float* __restrict__ bfc)
{
    const int n1 = BATCH * QKV_N;
    const int n2 = n1 + BATCH * HDIM;
    const int n3 = n2 + BATCH * DFF;
    for (int i = blockIdx.x * 256 + threadIdx.x; i < n3; i += gridDim.x * 256) {
        if (i < n1) {
            qkv[i] = battn[i % QKV_N];
        } else if (i < n2) {
            int j = i - n1;
            h[j] = bproj[j & (HDIM - 1)] + hidden[j];
        } else {
            int j = i - n2;
            ffn[j] = bfc[j & (DFF - 1)];
        }
    }
}

// ---------------- fc2 prep: gelu(ffn) in place + out = h + b_fc2 ----------------
__global__ void __launch_bounds__(256) prep_fc2_kernel(
    float* __restrict__ ffn, float* __restrict__ out,
    const float* __restrict__ h, const float* __restrict__ bfc2)
{
    const int n1 = BATCH * DFF / 4;                 // gelu range (float4)
    const int n2 = n1 + BATCH * HDIM;               // out-init range (scalar)
    for (int i = blockIdx.x * 256 + threadIdx.x; i < n2; i += gridDim.x * 256) {
        if (i < n1) {
            float4 v = reinterpret_cast<float4*>(ffn)[i];
            v.x = gelu_exact(v.x); v.y = gelu_exact(v.y);
            v.z = gelu_exact(v.z); v.w = gelu_exact(v.w);
            reinterpret_cast<float4*>(ffn)[i] = v;
        } else {
            int j = i - n1;
            out[j] = h[j] + bfc2[j & (HDIM - 1)];
        }
    }
}

// ---------------- tensor-core GEMM: C[32,N] += A[32,K] @ W[K,N] ----------------
// 1xTF32 (A rna-rounded, W raw fp32 bits -> HW-truncated tf32).
// 3-stage cp.async ring, 3 CTAs/SM, ONE barrier per chunk.
// Wave-balanced uneven split-K: CTA y gets chunks [C*y/S, C*(y+1)/S).
// atomicAdd into bias-preinitialized C.
#define WS_FL (TKC*136)
#define AS_FL (32*36)
#define GEMM_SMEM (NSTAGE*(WS_FL+AS_FL)*4)
__global__ void __launch_bounds__(256, 3) gemm_tc(
    const float* __restrict__ A, const float* __restrict__ W,
    float* __restrict__ C, int K, int N)
{
    extern __shared__ float smp[];
    float (*Ws)[TKC][136] = reinterpret_cast<float(*)[TKC][136]>(smp);
    float (*As)[32][36]   = reinterpret_cast<float(*)[32][36]>(smp + NSTAGE * WS_FL);

    int tid = threadIdx.x;
    int lane = tid & 31, warp = tid >> 5;
    int m0 = (warp & 1) * 16;
    int n0w = (warp >> 1) * 32;
    int nblk = blockIdx.x * TN;

    int cchunks = K / TKC;
    int c0 = (int)(((long long)cchunks * blockIdx.y)       / gridDim.y);
    int c1 = (int)(((long long)cchunks * (blockIdx.y + 1)) / gridDim.y);
    int kbeg = c0 * TKC;
    int nchunk = c1 - c0;

    float acc[4][4] = {};

    int am = tid >> 3, ak = (tid & 7) * 4;   // A staging coords (1 seg/thread)
    int gr = lane >> 2, kq = lane & 3;       // fragment coords

    auto prefetch = [&](int chunk) {
        int kb = kbeg + chunk * TKC;
        int s = chunk % NSTAGE;
        cp_async16(&As[s][am][ak], &A[am * K + kb + ak]);
        #pragma unroll
        for (int it = 0; it < 4; ++it) {
            int idx = it * 256 + tid;
            int kk = idx >> 5, c4 = (idx & 31) * 4;
            cp_async16(&Ws[s][kk][c4], &W[(size_t)(kb + kk) * N + nblk + c4]);
        }
    };

    #pragma unroll
    for (int c = 0; c < NSTAGE - 1; ++c) {
        if (c < nchunk) prefetch(c);
        cp_commit();
    }

    for (int i = 0; i < nchunk; ++i) {
        cp_wait<NSTAGE - 2>();    // group i complete
        __syncthreads();          // all warps done with compute(i-1) and see stage i
        if (i + NSTAGE - 1 < nchunk) prefetch(i + NSTAGE - 1);
        cp_commit();
        int s = i % NSTAGE;
        #pragma unroll
        for (int ks = 0; ks < 4; ++ks) {
            int k0 = ks * 8;
            unsigned ah[4];
            ah[0] = rna_tf32(As[s][m0 + gr    ][k0 + kq    ]);
            ah[1] = rna_tf32(As[s][m0 + gr + 8][k0 + kq    ]);
            ah[2] = rna_tf32(As[s][m0 + gr    ][k0 + kq + 4]);
            ah[3] = rna_tf32(As[s][m0 + gr + 8][k0 + kq + 4]);
            #pragma unroll
            for (int nt = 0; nt < 4; ++nt) {
                int nb2 = n0w + nt * 8 + gr;
                unsigned bh0 = __float_as_uint(Ws[s][k0 + kq    ][nb2]);
                unsigned bh1 = __float_as_uint(Ws[s][k0 + kq + 4][nb2]);
                mma_tf32(acc[nt], ah, bh0, bh1);
            }
        }
    }

    int cq = (lane & 3) * 2;
    #pragma unroll
    for (int nt = 0; nt < 4; ++nt) {
        int col = nblk + n0w + nt * 8 + cq;
        atomicAdd(&C[(m0 + gr    ) * N + col    ], acc[nt][0]);
        atomicAdd(&C[(m0 + gr    ) * N + col + 1], acc[nt][1]);
        atomicAdd(&C[(m0 + gr + 8) * N + col    ], acc[nt][2]);
        atomicAdd(&C[(m0 + gr + 8) * N + col + 1], acc[nt][3]);
    }
}

// ---------------- attention partial: one block per (b,h,page) ----------------
__global__ void __launch_bounds__(256) attn_partial(
    const float* __restrict__ qkv, const float* __restrict__ kv,
    const int* __restrict__ bt, const int* __restrict__ sl,
    float* __restrict__ pm, float* __restrict__ ps, float* __restrict__ pa)
{
    int b = blockIdx.x, h = blockIdx.y, sp = blockIdx.z;
    int tid = threadIdx.x, lane = tid & 31, w = tid >> 5;
    int pidx = (b * NHEADS + h) * NSPLIT + sp;
    int seq = sl[b];
    int t0 = sp * CHUNK;
    if (t0 >= seq) {
        if (tid == 0) { pm[pidx] = -INFINITY; ps[pidx] = 0.f; }
        return;
    }
    int nt = seq - t0; if (nt > CHUNK) nt = CHUNK;

    __shared__ float qs[HEADD];
    __shared__ float sc[CHUNK];
    __shared__ int   rbs;              // page base (float index, < 2^31)
    __shared__ float red[9];
    __shared__ float sa[2][HEADD];

    if (tid < HEADD) qs[tid] = qkv[b * QKV_N + h * HEADD + tid];
    if (tid == 0)
        rbs = bt[b * MAXBLK + sp] * (PAGE * NHEADS * HEADD) + h * HEADD;
    __syncthreads();
    int rb = rbs;

    const float scale = 0.08838834764831845f;  // 1/sqrt(128)
    float4 qx = reinterpret_cast<const float4*>(qs)[lane];

    // pass 1: scores. 4 tokens/warp/iter (loads clamped to page row 63 — always
    // resident; stores guarded by nt). Interleaved shfl chains pipeline.
    for (int tb = w * 4; tb < nt; tb += 32) {
        int u1 = min(tb + 1, 63), u2 = min(tb + 2, 63), u3 = min(tb + 3, 63);
        const float* base = kv + rb;
        float4 ka = reinterpret_cast<const float4*>(base + tb * (NHEADS * HEADD))[lane];
        float4 kb2 = reinterpret_cast<const float4*>(base + u1 * (NHEADS * HEADD))[lane];
        float4 kc2 = reinterpret_cast<const float4*>(base + u2 * (NHEADS * HEADD))[lane];
        float4 kd2 = reinterpret_cast<const float4*>(base + u3 * (NHEADS * HEADD))[lane];
        float d0 = ka.x  * qx.x + ka.y  * qx.y + ka.z  * qx.z + ka.w  * qx.w;
        float d1 = kb2.x * qx.x + kb2.y * qx.y + kb2.z * qx.z + kb2.w * qx.w;
        float d2 = kc2.x * qx.x + kc2.y * qx.y + kc2.z * qx.z + kc2.w * qx.w;
        float d3 = kd2.x * qx.x + kd2.y * qx.y + kd2.z * qx.z + kd2.w * qx.w;
        #pragma unroll
        for (int o = 16; o; o >>= 1) {
            d0 += __shfl_xor_sync(0xffffffffu, d0, o);
            d1 += __shfl_xor_sync(0xffffffffu, d1, o);
            d2 += __shfl_xor_sync(0xffffffffu, d2, o);
            d3 += __shfl_xor_sync(0xffffffffu, d3, o);
        }
        if (lane == 0) {
            sc[tb] = d0 * scale;
            if (tb + 1 < nt) sc[tb + 1] = d1 * scale;
            if (tb + 2 < nt) sc[tb + 2] = d2 * scale;
            if (tb + 3 < nt) sc[tb + 3] = d3 * scale;
        }
    }
    __syncthreads();

    // local max
    float m = -INFINITY;
    if (tid < nt) m = sc[tid];
    #pragma unroll
    for (int o = 16; o; o >>= 1) m = fmaxf(m, __shfl_xor_sync(0xffffffffu, m, o));
    if (lane == 0) red[w] = m;
    __syncthreads();
    if (tid == 0) {
        float mm = red[0];
        #pragma unroll
        for (int i = 1; i < 8; i++) mm = fmaxf(mm, red[i]);
        red[8] = mm;
    }
    __syncthreads();
    float M = red[8];
    __syncthreads();

    // exp + local sum
    float s = 0.f;
    if (tid < nt) {
        float e = __expf(sc[tid] - M);
        sc[tid] = e; s = e;
    }
    #pragma unroll
    for (int o = 16; o; o >>= 1) s += __shfl_xor_sync(0xffffffffu, s, o);
    if (lane == 0) red[w] = s;
    __syncthreads();
    if (tid == 0) {
        float S = 0.f;
        #pragma unroll
        for (int i = 0; i < 8; i++) S += red[i];
        pm[pidx] = M; ps[pidx] = S;
    }

    // pass 2: unnormalized weighted V. 2 halves x 4-way unroll.
    int d = tid & 127, half = tid >> 7;
    const float* Vb = kv + (size_t)NUMBLK * PAGE * NHEADS * HEADD;
    float a0 = 0.f, a1 = 0.f, a2 = 0.f, a3 = 0.f;
    int t = half;
    for (; t + 6 < nt; t += 8) {
        const float* v0 = Vb + rb + (t    ) * (NHEADS * HEADD);
        const float* v1 = Vb + rb + (t + 2) * (NHEADS * HEADD);
        const float* v2 = Vb + rb + (t + 4) * (NHEADS * HEADD);
        const float* v3 = Vb + rb + (t + 6) * (NHEADS * HEADD);
        a0 += sc[t    ] * v0[d];
        a1 += sc[t + 2] * v1[d];
        a2 += sc[t + 4] * v2[d];
        a3 += sc[t + 6] * v3[d];
    }
    for (; t < nt; t += 2) {
        const float* vr = Vb + rb + t * (NHEADS * HEADD);
        a0 += sc[t] * vr[d];
    }
    sa[half][d] = (a0 + a1) + (a2 + a3);
    __syncthreads();
    if (tid < HEADD) pa[(size_t)pidx * HEADD + tid] = sa[0][tid] + sa[1][tid];
}

// ---------------- attention combine: one block per (b,h) ----------------
__global__ void __launch_bounds__(128) attn_combine(
    const float* __restrict__ pm, const float* __restrict__ ps,
    const float* __restrict__ pa, float* __restrict__ out)
{
    int b = blockIdx.x, h = blockIdx.y;
    int idx = b * NHEADS + h;
    int tid = threadIdx.x;
    __shared__ float ms[NSPLIT], ss[NSPLIT];
    if (tid < NSPLIT) {
        ms[tid] = pm[idx * NSPLIT + tid];
        ss[tid] = ps[idx * NSPLIT + tid];
    }
    __syncthreads();
    float M = -INFINITY;
    #pragma unroll
    for (int i = 0; i < NSPLIT; i++)
        if (ss[i] > 0.f) M = fmaxf(M, ms[i]);
    float num = 0.f, den = 0.f;
    #pragma unroll
    for (int i = 0; i < NSPLIT; i++) {
        if (ss[i] > 0.f) {
            float wv = __expf(ms[i] - M);
            den += wv * ss[i];
            num += wv * pa[((size_t)idx * NSPLIT + i) * HEADD + tid];
        }
    }
    out[b * HDIM + h * HEADD + tid] = num / den;
}

// ---------------- host launcher ----------------
extern "C" void kernel_launch(void* const* d_in, const int* in_sizes, int n_in,
                              void* d_out, int out_size)
{
    const float* hidden = (const float*)d_in[0];
    const float* kv     = (const float*)d_in[1];
    const int*   bt     = (const int*)d_in[2];
    const int*   sl     = (const int*)d_in[3];
    int p = (n_in > 4 && in_sizes[4] == 1) ? 5 : 4;  // skip max_seq_len if present
    const float* ln1g  = (const float*)d_in[p + 0];
    const float* ln1b  = (const float*)d_in[p + 1];
    const float* ln2g  = (const float*)d_in[p + 2];
    const float* ln2b  = (const float*)d_in[p + 3];
    const float* wattn = (const float*)d_in[p + 4];
    const float* battn = (const float*)d_in[p + 5];
    const float* wproj = (const float*)d_in[p + 6];
    const float* bproj = (const float*)d_in[p + 7];
    const float* wfc   = (const float*)d_in[p + 8];
    const float* bfc   = (const float*)d_in[p + 9];
    const float* wfc2  = (const float*)d_in[p + 10];
    const float* bfc2  = (const float*)d_in[p + 11];
    float* out = (float*)d_out;

    float *x1, *qkvp, *att, *h, *x2, *ffn, *pm, *ps, *pa;
    cudaGetSymbolAddress((void**)&x1,   g_x1);
    cudaGetSymbolAddress((void**)&qkvp, g_qkv);
    cudaGetSymbolAddress((void**)&att,  g_att);
    cudaGetSymbolAddress((void**)&h,    g_h);
    cudaGetSymbolAddress((void**)&x2,   g_x2);
    cudaGetSymbolAddress((void**)&ffn,  g_ffn);
    cudaGetSymbolAddress((void**)&pm,   g_pm);
    cudaGetSymbolAddress((void**)&ps,   g_ps);
    cudaGetSymbolAddress((void**)&pa,   g_pa);

    cudaFuncSetAttribute(gemm_tc,
        cudaFuncAttributeMaxDynamicSharedMemorySize, GEMM_SMEM);

    // 1. ln1 + merged bias/residual inits
    ln_kernel<<<BATCH, 256>>>(hidden, ln1g, ln1b, x1);
    init3_kernel<<<512, 256>>>(qkvp, battn, h, bproj, hidden, ffn, bfc);
    // 2. qkv = x1 @ w_attn + b_attn   (48 x 6 = 288 CTAs, ~11 chunks each, 1 wave)
    gemm_tc<<<dim3(QKV_N / TN, 6), 256, GEMM_SMEM>>>(x1, wattn, qkvp, HDIM, QKV_N);
    // 3. attention (flash-decode, 32-way page split)
    attn_partial<<<dim3(BATCH, NHEADS, NSPLIT), 256>>>(qkvp, kv, bt, sl, pm, ps, pa);
    attn_combine<<<dim3(BATCH, NHEADS), 128>>>(pm, ps, pa, att);
    // 4. h += attn @ w_proj   (16 x 18 = 288 CTAs, 3-4 chunks each, 1 wave)
    gemm_tc<<<dim3(HDIM / TN, 18), 256, GEMM_SMEM>>>(att, wproj, h, HDIM, HDIM);
    // 5. ln2
    ln_kernel<<<BATCH, 256>>>(h, ln2g, ln2b, x2);
    // 6. ffn += x2 @ w_fc   (64 x 4 = 256 CTAs, 16 chunks each, 1 wave)
    gemm_tc<<<dim3(DFF / TN, 4), 256, GEMM_SMEM>>>(x2, wfc, ffn, HDIM, DFF);
    // 6b. gelu(ffn) + out = h + b_fc2 (one kernel)
    prep_fc2_kernel<<<296, 256>>>(ffn, out, h, bfc2);
    // 7. out += gelu(ffn) @ w_fc2   (16 x 18 = 288 CTAs, ~14 chunks each, 1 wave)
    gemm_tc<<<dim3(HDIM / TN, 18), 256, GEMM_SMEM>>>(ffn, wfc2, out, DFF, HDIM);
}

// round 12
// speedup vs baseline: 1.1417x; 1.0203x over previous
#include <cuda_runtime.h>
#include <cuda_bf16.h>
#include <math.h>

// ---------------- constants ----------------
#define BATCH   32
#define HDIM    2048
#define NHEADS  16
#define HEADD   128
#define DFF     8192
#define QKV_N   (3*HDIM)   // 6144
#define MAXS    2048
#define MAXBLK  32
#define PAGE    64
#define NUMBLK  1024
#define NSPLIT  32
#define CHUNK   64         // MAXS / NSPLIT == one KV page
#define TKC     32         // gemm k-chunk
#define TN      128        // gemm n-tile
#define NSTAGE  3          // gemm pipeline stages

// ---------------- scratch (no allocs allowed) ----------------
__device__ float g_x1 [BATCH*HDIM];
__device__ float g_q  [BATCH*HDIM];      // only Q is needed (ref discards K,V cols)
__device__ float g_att[BATCH*HDIM];
__device__ float g_h  [BATCH*HDIM];
__device__ float g_x2 [BATCH*HDIM];
__device__ float g_ffn[BATCH*DFF];
__device__ float g_pm [BATCH*NHEADS*NSPLIT];
__device__ float g_ps [BATCH*NHEADS*NSPLIT];
__device__ float g_pa [BATCH*NHEADS*NSPLIT*HEADD];

// ---------------- helpers ----------------
__device__ __forceinline__ float gelu_exact(float x) {
    return 0.5f * x * (1.0f + erff(x * 0.70710678118654752f));
}

// unbiased rounding to tf32 (A and W — biased truncation measured 2x worse err)
__device__ __forceinline__ unsigned rna_tf32(float x) {
    unsigned h;
    asm("cvt.rna.tf32.f32 %0, %1;" : "=r"(h) : "f"(x));
    return h;
}

__device__ __forceinline__ void mma_tf32(float d[4], const unsigned a[4],
                                         unsigned b0, unsigned b1) {
    asm volatile(
        "mma.sync.aligned.m16n8k8.row.col.f32.tf32.tf32.f32 "
        "{%0,%1,%2,%3}, {%4,%5,%6,%7}, {%8,%9}, {%0,%1,%2,%3};"
        : "+f"(d[0]), "+f"(d[1]), "+f"(d[2]), "+f"(d[3])
        : "r"(a[0]), "r"(a[1]), "r"(a[2]), "r"(a[3]), "r"(b0), "r"(b1));
}

__device__ __forceinline__ void cp_async16(void* smem, const void* g) {
    unsigned s = (unsigned)__cvta_generic_to_shared(smem);
    asm volatile("cp.async.cg.shared.global [%0], [%1], 16;" :: "r"(s), "l"(g));
}
__device__ __forceinline__ void cp_commit() {
    asm volatile("cp.async.commit_group;");
}
template<int N>
__device__ __forceinline__ void cp_wait() {
    asm volatile("cp.async.wait_group %0;" :: "n"(N));
}

// ---------------- LayerNorm: 32 rows x 2048 ----------------
__global__ void __launch_bounds__(256) ln_kernel(
    const float* __restrict__ x, const float* __restrict__ g,
    const float* __restrict__ b, float* __restrict__ y)
{
    int row = blockIdx.x;
    const float* xr = x + row * HDIM;
    float s = 0.f, s2 = 0.f;
    for (int i = threadIdx.x; i < HDIM; i += 256) {
        float v = xr[i]; s += v; s2 += v * v;
    }
    __shared__ float sh[16];
    int lane = threadIdx.x & 31, w = threadIdx.x >> 5;
    #pragma unroll
    for (int o = 16; o; o >>= 1) {
        s  += __shfl_xor_sync(0xffffffffu, s,  o);
        s2 += __shfl_xor_sync(0xffffffffu, s2, o);
    }
    if (lane == 0) { sh[w] = s; sh[8 + w] = s2; }
    __syncthreads();
    if (threadIdx.x == 0) {
        float S = 0.f, S2 = 0.f;
        #pragma unroll
        for (int i = 0; i < 8; i++) { S += sh[i]; S2 += sh[8 + i]; }
        sh[0] = S; sh[1] = S2;
    }
    __syncthreads();
    float mu  = sh[0] * (1.0f / HDIM);
    float var = sh[1] * (1.0f / HDIM) - mu * mu;
    float inv = rsqrtf(var + 1e-5f);
    float* yr = y + row * HDIM;
    for (int i = threadIdx.x; i < HDIM; i += 256)
        yr[i] = (xr[i] - mu) * inv * g[i] + b[i];
}

// ---------------- merged init: q=bq, h=bproj+res, ffn=bfc ----------------
__global__ void __launch_bounds__(256) init3_kernel(
    float* __restrict__ q, const float* __restrict__ battn,
    float* __restrict__ h, const float* __restrict__ bproj,
    const float* __restrict__ hidden,
    float* __restrict__ ffn, const float* __restrict__ bfc)
{
    const int n1 = BATCH * HDIM;              // q (bias = battn[0:H])
    const int n2 = n1 + BATCH * HDIM;         // h
    const int n3 = n2 + BATCH * DFF;          // ffn
    for (int i = blockIdx.x * 256 + threadIdx.x; i < n3; i += gridDim.x * 256) {
        if (i < n1) {
            q[i] = battn[i & (HDIM - 1)];
        } else if (i < n2) {
            int j = i - n1;
            h[j] = bproj[j & (HDIM - 1)] + hidden[j];
        } else {
            int j = i - n2;
            ffn[j] = bfc[j & (DFF - 1)];
        }
    }
}

// ---------------- fc2 prep: gelu(ffn) in place + out = h + b_fc2 ----------------
__global__ void __launch_bounds__(256) prep_fc2_kernel(
    float* __restrict__ ffn, float* __restrict__ out,
    const float* __restrict__ h, const float* __restrict__ bfc2)
{
    const int n1 = BATCH * DFF / 4;                 // gelu range (float4)
    const int n2 = n1 + BATCH * HDIM;               // out-init range (scalar)
    for (int i = blockIdx.x * 256 + threadIdx.x; i < n2; i += gridDim.x * 256) {
        if (i < n1) {
            float4 v = reinterpret_cast<float4*>(ffn)[i];
            v.x = gelu_exact(v.x); v.y = gelu_exact(v.y);
            v.z = gelu_exact(v.z); v.w = gelu_exact(v.w);
            reinterpret_cast<float4*>(ffn)[i] = v;
        } else {
            int j = i - n1;
            out[j] = h[j] + bfc2[j & (HDIM - 1)];
        }
    }
}

// ---------------- tensor-core GEMM: C[32,Nout] += A[32,K] @ W[K,:Nout] ----------------
// 1xTF32, A and W rna-rounded (unbiased). 3-stage cp.async ring, 3 CTAs/SM,
// one barrier per chunk. ldW = W row stride (allows slicing w_attn to Q cols).
// Wave-balanced uneven split-K. atomicAdd into bias-preinitialized C.
#define WS_FL (TKC*136)
#define AS_FL (32*36)
#define GEMM_SMEM (NSTAGE*(WS_FL+AS_FL)*4)
__global__ void __launch_bounds__(256, 3) gemm_tc(
    const float* __restrict__ A, const float* __restrict__ W,
    float* __restrict__ C, int K, int Nout, int ldW)
{
    extern __shared__ float smp[];
    float (*Ws)[TKC][136] = reinterpret_cast<float(*)[TKC][136]>(smp);
    float (*As)[32][36]   = reinterpret_cast<float(*)[32][36]>(smp + NSTAGE * WS_FL);

    int tid = threadIdx.x;
    int lane = tid & 31, warp = tid >> 5;
    int m0 = (warp & 1) * 16;
    int n0w = (warp >> 1) * 32;
    int nblk = blockIdx.x * TN;

    int cchunks = K / TKC;
    int c0 = (int)(((long long)cchunks * blockIdx.y)       / gridDim.y);
    int c1 = (int)(((long long)cchunks * (blockIdx.y + 1)) / gridDim.y);
    int kbeg = c0 * TKC;
    int nchunk = c1 - c0;

    float acc[4][4] = {};

    int am = tid >> 3, ak = (tid & 7) * 4;   // A staging coords (1 seg/thread)
    int gr = lane >> 2, kq = lane & 3;       // fragment coords

    auto prefetch = [&](int chunk) {
        int kb = kbeg + chunk * TKC;
        int s = chunk % NSTAGE;
        cp_async16(&As[s][am][ak], &A[am * K + kb + ak]);
        #pragma unroll
        for (int it = 0; it < 4; ++it) {
            int idx = it * 256 + tid;
            int kk = idx >> 5, c4 = (idx & 31) * 4;
            cp_async16(&Ws[s][kk][c4], &W[(size_t)(kb + kk) * ldW + nblk + c4]);
        }
    };

    #pragma unroll
    for (int c = 0; c < NSTAGE - 1; ++c) {
        if (c < nchunk) prefetch(c);
        cp_commit();
    }

    for (int i = 0; i < nchunk; ++i) {
        cp_wait<NSTAGE - 2>();    // group i complete
        __syncthreads();          // all warps done with compute(i-1) and see stage i
        if (i + NSTAGE - 1 < nchunk) prefetch(i + NSTAGE - 1);
        cp_commit();
        int s = i % NSTAGE;
        #pragma unroll
        for (int ks = 0; ks < 4; ++ks) {
            int k0 = ks * 8;
            unsigned ah[4];
            ah[0] = rna_tf32(As[s][m0 + gr    ][k0 + kq    ]);
            ah[1] = rna_tf32(As[s][m0 + gr + 8][k0 + kq    ]);
            ah[2] = rna_tf32(As[s][m0 + gr    ][k0 + kq + 4]);
            ah[3] = rna_tf32(As[s][m0 + gr + 8][k0 + kq + 4]);
            #pragma unroll
            for (int nt = 0; nt < 4; ++nt) {
                int nb2 = n0w + nt * 8 + gr;
                unsigned bh0 = rna_tf32(Ws[s][k0 + kq    ][nb2]);
                unsigned bh1 = rna_tf32(Ws[s][k0 + kq + 4][nb2]);
                mma_tf32(acc[nt], ah, bh0, bh1);
            }
        }
    }

    int cq = (lane & 3) * 2;
    #pragma unroll
    for (int nt = 0; nt < 4; ++nt) {
        int col = nblk + n0w + nt * 8 + cq;
        atomicAdd(&C[(m0 + gr    ) * Nout + col    ], acc[nt][0]);
        atomicAdd(&C[(m0 + gr    ) * Nout + col + 1], acc[nt][1]);
        atomicAdd(&C[(m0 + gr + 8) * Nout + col    ], acc[nt][2]);
        atomicAdd(&C[(m0 + gr + 8) * Nout + col + 1], acc[nt][3]);
    }
}

// ---------------- attention partial: one block per (b,h,page) ----------------
__global__ void __launch_bounds__(256) attn_partial(
    const float* __restrict__ q, const float* __restrict__ kv,
    const int* __restrict__ bt, const int* __restrict__ sl,
    float* __restrict__ pm, float* __restrict__ ps, float* __restrict__ pa)
{
    int b = blockIdx.x, h = blockIdx.y, sp = blockIdx.z;
    int tid = threadIdx.x, lane = tid & 31, w = tid >> 5;
    int pidx = (b * NHEADS + h) * NSPLIT + sp;
    int seq = sl[b];
    int t0 = sp * CHUNK;
    if (t0 >= seq) {
        if (tid == 0) { pm[pidx] = -INFINITY; ps[pidx] = 0.f; }
        return;
    }
    int nt = seq - t0; if (nt > CHUNK) nt = CHUNK;

    __shared__ float qs[HEADD];
    __shared__ float sc[CHUNK];
    __shared__ int   rbs;              // page base (float index, < 2^31)
    __shared__ float red[9];
    __shared__ float sa[2][HEADD];

    if (tid < HEADD) qs[tid] = q[b * HDIM + h * HEADD + tid];
    if (tid == 0)
        rbs = bt[b * MAXBLK + sp] * (PAGE * NHEADS * HEADD) + h * HEADD;
    __syncthreads();
    int rb = rbs;

    const float scale = 0.08838834764831845f;  // 1/sqrt(128)
    float4 qx = reinterpret_cast<const float4*>(qs)[lane];

    // pass 1: scores. 4 tokens/warp/iter (loads clamped to page row 63 — always
    // resident; stores guarded by nt). Interleaved shfl chains pipeline.
    for (int tb = w * 4; tb < nt; tb += 32) {
        int u1 = min(tb + 1, 63), u2 = min(tb + 2, 63), u3 = min(tb + 3, 63);
        const float* base = kv + rb;
        float4 ka = reinterpret_cast<const float4*>(base + tb * (NHEADS * HEADD))[lane];
        float4 kb2 = reinterpret_cast<const float4*>(base + u1 * (NHEADS * HEADD))[lane];
        float4 kc2 = reinterpret_cast<const float4*>(base + u2 * (NHEADS * HEADD))[lane];
        float4 kd2 = reinterpret_cast<const float4*>(base + u3 * (NHEADS * HEADD))[lane];
        float d0 = ka.x  * qx.x + ka.y  * qx.y + ka.z  * qx.z + ka.w  * qx.w;
        float d1 = kb2.x * qx.x + kb2.y * qx.y + kb2.z * qx.z + kb2.w * qx.w;
        float d2 = kc2.x * qx.x + kc2.y * qx.y + kc2.z * qx.z + kc2.w * qx.w;
        float d3 = kd2.x * qx.x + kd2.y * qx.y + kd2.z * qx.z + kd2.w * qx.w;
        #pragma unroll
        for (int o = 16; o; o >>= 1) {
            d0 += __shfl_xor_sync(0xffffffffu, d0, o);
            d1 += __shfl_xor_sync(0xffffffffu, d1, o);
            d2 += __shfl_xor_sync(0xffffffffu, d2, o);
            d3 += __shfl_xor_sync(0xffffffffu, d3, o);
        }
        if (lane == 0) {
            sc[tb] = d0 * scale;
            if (tb + 1 < nt) sc[tb + 1] = d1 * scale;
            if (tb + 2 < nt) sc[tb + 2] = d2 * scale;
            if (tb + 3 < nt) sc[tb + 3] = d3 * scale;
        }
    }
    __syncthreads();

    // local max
    float m = -INFINITY;
    if (tid < nt) m = sc[tid];
    #pragma unroll
    for (int o = 16; o; o >>= 1) m = fmaxf(m, __shfl_xor_sync(0xffffffffu, m, o));
    if (lane == 0) red[w] = m;
    __syncthreads();
    if (tid == 0) {
        float mm = red[0];
        #pragma unroll
        for (int i = 1; i < 8; i++) mm = fmaxf(mm, red[i]);
        red[8] = mm;
    }
    __syncthreads();
    float M = red[8];
    __syncthreads();

    // exp + local sum
    float s = 0.f;
    if (tid < nt) {
        float e = __expf(sc[tid] - M);
        sc[tid] = e; s = e;
    }
    #pragma unroll
    for (int o = 16; o; o >>= 1) s += __shfl_xor_sync(0xffffffffu, s, o);
    if (lane == 0) red[w] = s;
    __syncthreads();
    if (tid == 0) {
        float S = 0.f;
        #pragma unroll
        for (int i = 0; i < 8; i++) S += red[i];
        pm[pidx] = M; ps[pidx] = S;
    }

    // pass 2: unnormalized weighted V. 2 halves x 4-way unroll.
    int d = tid & 127, half = tid >> 7;
    const float* Vb = kv + (size_t)NUMBLK * PAGE * NHEADS * HEADD;
    float a0 = 0.f, a1 = 0.f, a2 = 0.f, a3 = 0.f;
    int t = half;
    for (; t + 6 < nt; t += 8) {
        const float* v0 = Vb + rb + (t    ) * (NHEADS * HEADD);
        const float* v1 = Vb + rb + (t + 2) * (NHEADS * HEADD);
        const float* v2 = Vb + rb + (t + 4) * (NHEADS * HEADD);
        const float* v3 = Vb + rb + (t + 6) * (NHEADS * HEADD);
        a0 += sc[t    ] * v0[d];
        a1 += sc[t + 2] * v1[d];
        a2 += sc[t + 4] * v2[d];
        a3 += sc[t + 6] * v3[d];
    }
    for (; t < nt; t += 2) {
        const float* vr = Vb + rb + t * (NHEADS * HEADD);
        a0 += sc[t] * vr[d];
    }
    sa[half][d] = (a0 + a1) + (a2 + a3);
    __syncthreads();
    if (tid < HEADD) pa[(size_t)pidx * HEADD + tid] = sa[0][tid] + sa[1][tid];
}

// ---------------- attention combine: one block per (b,h) ----------------
__global__ void __launch_bounds__(128) attn_combine(
    const float* __restrict__ pm, const float* __restrict__ ps,
    const float* __restrict__ pa, float* __restrict__ out)
{
    int b = blockIdx.x, h = blockIdx.y;
    int idx = b * NHEADS + h;
    int tid = threadIdx.x;
    __shared__ float ms[NSPLIT], ss[NSPLIT];
    if (tid < NSPLIT) {
        ms[tid] = pm[idx * NSPLIT + tid];
        ss[tid] = ps[idx * NSPLIT + tid];
    }
    __syncthreads();
    float M = -INFINITY;
    #pragma unroll
    for (int i = 0; i < NSPLIT; i++)
        if (ss[i] > 0.f) M = fmaxf(M, ms[i]);
    float num = 0.f, den = 0.f;
    #pragma unroll
    for (int i = 0; i < NSPLIT; i++) {
        if (ss[i] > 0.f) {
            float wv = __expf(ms[i] - M);
            den += wv * ss[i];
            num += wv * pa[((size_t)idx * NSPLIT + i) * HEADD + tid];
        }
    }
    out[b * HDIM + h * HEADD + tid] = num / den;
}

// ---------------- host launcher ----------------
extern "C" void kernel_launch(void* const* d_in, const int* in_sizes, int n_in,
                              void* d_out, int out_size)
{
    const float* hidden = (const float*)d_in[0];
    const float* kv     = (const float*)d_in[1];
    const int*   bt     = (const int*)d_in[2];
    const int*   sl     = (const int*)d_in[3];
    int p = (n_in > 4 && in_sizes[4] == 1) ? 5 : 4;  // skip max_seq_len if present
    const float* ln1g  = (const float*)d_in[p + 0];
    const float* ln1b  = (const float*)d_in[p + 1];
    const float* ln2g  = (const float*)d_in[p + 2];
    const float* ln2b  = (const float*)d_in[p + 3];
    const float* wattn = (const float*)d_in[p + 4];
    const float* battn = (const float*)d_in[p + 5];
    const float* wproj = (const float*)d_in[p + 6];
    const float* bproj = (const float*)d_in[p + 7];
    const float* wfc   = (const float*)d_in[p + 8];
    const float* bfc   = (const float*)d_in[p + 9];
    const float* wfc2  = (const float*)d_in[p + 10];
    const float* bfc2  = (const float*)d_in[p + 11];
    float* out = (float*)d_out;

    float *x1, *qbuf, *att, *h, *x2, *ffn, *pm, *ps, *pa;
    cudaGetSymbolAddress((void**)&x1,   g_x1);
    cudaGetSymbolAddress((void**)&qbuf, g_q);
    cudaGetSymbolAddress((void**)&att,  g_att);
    cudaGetSymbolAddress((void**)&h,    g_h);
    cudaGetSymbolAddress((void**)&x2,   g_x2);
    cudaGetSymbolAddress((void**)&ffn,  g_ffn);
    cudaGetSymbolAddress((void**)&pm,   g_pm);
    cudaGetSymbolAddress((void**)&ps,   g_ps);
    cudaGetSymbolAddress((void**)&pa,   g_pa);

    cudaFuncSetAttribute(gemm_tc,
        cudaFuncAttributeMaxDynamicSharedMemorySize, GEMM_SMEM);

    // 1. ln1 + merged bias/residual inits
    ln_kernel<<<BATCH, 256>>>(hidden, ln1g, ln1b, x1);
    init3_kernel<<<448, 256>>>(qbuf, battn, h, bproj, hidden, ffn, bfc);
    // 2. q = x1 @ w_attn[:, :H] + b_attn[:H]   (K,V cols of qkv are unused by ref!)
    //    16 x 18 = 288 CTAs, 1 wave. ldW = QKV_N.
    gemm_tc<<<dim3(HDIM / TN, 18), 256, GEMM_SMEM>>>(x1, wattn, qbuf, HDIM, HDIM, QKV_N);
    // 3. attention (flash-decode, 32-way page split)
    attn_partial<<<dim3(BATCH, NHEADS, NSPLIT), 256>>>(qbuf, kv, bt, sl, pm, ps, pa);
    attn_combine<<<dim3(BATCH, NHEADS), 128>>>(pm, ps, pa, att);
    // 4. h += attn @ w_proj   (16 x 18 = 288 CTAs, 1 wave)
    gemm_tc<<<dim3(HDIM / TN, 18), 256, GEMM_SMEM>>>(att, wproj, h, HDIM, HDIM, HDIM);
    // 5. ln2
    ln_kernel<<<BATCH, 256>>>(h, ln2g, ln2b, x2);
    // 6. ffn += x2 @ w_fc   (64 x 4 = 256 CTAs, 16 chunks each, 1 wave)
    gemm_tc<<<dim3(DFF / TN, 4), 256, GEMM_SMEM>>>(x2, wfc, ffn, HDIM, DFF, DFF);
    // 6b. gelu(ffn) + out = h + b_fc2 (one kernel)
    prep_fc2_kernel<<<296, 256>>>(ffn, out, h, bfc2);
    // 7. out += gelu(ffn) @ w_fc2   (16 x 18 = 288 CTAs, ~14 chunks each, 1 wave)
    gemm_tc<<<dim3(HDIM / TN, 18), 256, GEMM_SMEM>>>(ffn, wfc2, out, DFF, HDIM, HDIM);
}

// round 13
// speedup vs baseline: 1.1703x; 1.0251x over previous
#include <cuda_runtime.h>
#include <cuda_bf16.h>
#include <math.h>

// ---------------- constants ----------------
#define BATCH   32
#define HDIM    2048
#define NHEADS  16
#define HEADD   128
#define DFF     8192
#define QKV_N   (3*HDIM)   // 6144
#define MAXS    2048
#define MAXBLK  32
#define PAGE    64
#define NUMBLK  1024
#define NSPLIT  32
#define CHUNK   64         // MAXS / NSPLIT == one KV page
#define TKC     32         // gemm k-chunk
#define TN      128        // gemm n-tile
#define NSTAGE  3          // gemm pipeline stages

// ---------------- scratch (no allocs allowed) ----------------
__device__ float g_x1 [BATCH*HDIM];
__device__ float g_q  [BATCH*HDIM];      // only Q is needed (ref discards K,V cols)
__device__ float g_att[BATCH*HDIM];
__device__ float g_h  [BATCH*HDIM];
__device__ float g_x2 [BATCH*HDIM];
__device__ float g_ffn[BATCH*DFF];
__device__ float g_pm [BATCH*NHEADS*NSPLIT];
__device__ float g_ps [BATCH*NHEADS*NSPLIT];
__device__ float g_pa [BATCH*NHEADS*NSPLIT*HEADD];

// ---------------- helpers ----------------
__device__ __forceinline__ float gelu_exact(float x) {
    return 0.5f * x * (1.0f + erff(x * 0.70710678118654752f));
}

// unbiased rounding to tf32 (A and W — biased truncation measured 2x worse err)
__device__ __forceinline__ unsigned rna_tf32(float x) {
    unsigned h;
    asm("cvt.rna.tf32.f32 %0, %1;" : "=r"(h) : "f"(x));
    return h;
}

__device__ __forceinline__ void mma_tf32(float d[4], const unsigned a[4],
                                         unsigned b0, unsigned b1) {
    asm volatile(
        "mma.sync.aligned.m16n8k8.row.col.f32.tf32.tf32.f32 "
        "{%0,%1,%2,%3}, {%4,%5,%6,%7}, {%8,%9}, {%0,%1,%2,%3};"
        : "+f"(d[0]), "+f"(d[1]), "+f"(d[2]), "+f"(d[3])
        : "r"(a[0]), "r"(a[1]), "r"(a[2]), "r"(a[3]), "r"(b0), "r"(b1));
}

__device__ __forceinline__ void cp_async16(void* smem, const void* g) {
    unsigned s = (unsigned)__cvta_generic_to_shared(smem);
    asm volatile("cp.async.cg.shared.global [%0], [%1], 16;" :: "r"(s), "l"(g));
}
__device__ __forceinline__ void cp_commit() {
    asm volatile("cp.async.commit_group;");
}
template<int N>
__device__ __forceinline__ void cp_wait() {
    asm volatile("cp.async.wait_group %0;" :: "n"(N));
}

// ---------------- LN body (one block, one row) ----------------
__device__ __forceinline__ void ln_row(
    const float* __restrict__ xr, const float* __restrict__ g,
    const float* __restrict__ b, float* __restrict__ yr)
{
    float s = 0.f, s2 = 0.f;
    for (int i = threadIdx.x; i < HDIM; i += 256) {
        float v = xr[i]; s += v; s2 += v * v;
    }
    __shared__ float sh[16];
    int lane = threadIdx.x & 31, w = threadIdx.x >> 5;
    #pragma unroll
    for (int o = 16; o; o >>= 1) {
        s  += __shfl_xor_sync(0xffffffffu, s,  o);
        s2 += __shfl_xor_sync(0xffffffffu, s2, o);
    }
    if (lane == 0) { sh[w] = s; sh[8 + w] = s2; }
    __syncthreads();
    if (threadIdx.x == 0) {
        float S = 0.f, S2 = 0.f;
        #pragma unroll
        for (int i = 0; i < 8; i++) { S += sh[i]; S2 += sh[8 + i]; }
        sh[0] = S; sh[1] = S2;
    }
    __syncthreads();
    float mu  = sh[0] * (1.0f / HDIM);
    float var = sh[1] * (1.0f / HDIM) - mu * mu;
    float inv = rsqrtf(var + 1e-5f);
    for (int i = threadIdx.x; i < HDIM; i += 256)
        yr[i] = (xr[i] - mu) * inv * g[i] + b[i];
}

// ---------------- phase 1: ln1 rows + init q/h/ffn (independent outputs) -----
__global__ void __launch_bounds__(256) ln1_init_kernel(
    const float* __restrict__ hidden,
    const float* __restrict__ ln1g, const float* __restrict__ ln1b,
    float* __restrict__ x1,
    float* __restrict__ q, const float* __restrict__ battn,
    float* __restrict__ h, const float* __restrict__ bproj,
    float* __restrict__ ffn, const float* __restrict__ bfc)
{
    if (blockIdx.x < BATCH) {
        int row = blockIdx.x;
        ln_row(hidden + row * HDIM, ln1g, ln1b, x1 + row * HDIM);
        return;
    }
    const int gix = blockIdx.x - BATCH;
    const int gnum = gridDim.x - BATCH;
    const int n1 = BATCH * HDIM;              // q
    const int n2 = n1 + BATCH * HDIM;         // h
    const int n3 = n2 + BATCH * DFF;          // ffn
    for (int i = gix * 256 + threadIdx.x; i < n3; i += gnum * 256) {
        if (i < n1) {
            q[i] = battn[i & (HDIM - 1)];
        } else if (i < n2) {
            int j = i - n1;
            h[j] = bproj[j & (HDIM - 1)] + hidden[j];
        } else {
            int j = i - n2;
            ffn[j] = bfc[j & (DFF - 1)];
        }
    }
}

// ---------------- phase 2: ln2 rows + out = h + b_fc2 (both depend on h) ----
__global__ void __launch_bounds__(256) ln2_init_kernel(
    const float* __restrict__ h,
    const float* __restrict__ ln2g, const float* __restrict__ ln2b,
    float* __restrict__ x2,
    float* __restrict__ out, const float* __restrict__ bfc2)
{
    if (blockIdx.x < BATCH) {
        int row = blockIdx.x;
        ln_row(h + row * HDIM, ln2g, ln2b, x2 + row * HDIM);
        return;
    }
    const int gix = blockIdx.x - BATCH;
    const int gnum = gridDim.x - BATCH;
    const int n = BATCH * HDIM;
    for (int i = gix * 256 + threadIdx.x; i < n; i += gnum * 256) {
        out[i] = h[i] + bfc2[i & (HDIM - 1)];
    }
}

// ---------------- elementwise gelu (in place, float4) ----------------
__global__ void __launch_bounds__(256) gelu_kernel(float* __restrict__ x, int n4)
{
    int i = blockIdx.x * 256 + threadIdx.x;
    if (i < n4) {
        float4 v = reinterpret_cast<float4*>(x)[i];
        v.x = gelu_exact(v.x); v.y = gelu_exact(v.y);
        v.z = gelu_exact(v.z); v.w = gelu_exact(v.w);
        reinterpret_cast<float4*>(x)[i] = v;
    }
}

// ---------------- tensor-core GEMM: C[32,Nout] += A[32,K] @ W[K,:Nout] -------
// 1xTF32, A and W rna-rounded (unbiased). 3-stage cp.async ring, 3 CTAs/SM,
// one barrier per chunk. ldW = W row stride (allows slicing w_attn to Q cols).
// Wave-balanced uneven split-K. atomicAdd into bias-preinitialized C.
#define WS_FL (TKC*136)
#define AS_FL (32*36)
#define GEMM_SMEM (NSTAGE*(WS_FL+AS_FL)*4)
__global__ void __launch_bounds__(256, 3) gemm_tc(
    const float* __restrict__ A, const float* __restrict__ W,
    float* __restrict__ C, int K, int Nout, int ldW)
{
    extern __shared__ float smp[];
    float (*Ws)[TKC][136] = reinterpret_cast<float(*)[TKC][136]>(smp);
    float (*As)[32][36]   = reinterpret_cast<float(*)[32][36]>(smp + NSTAGE * WS_FL);

    int tid = threadIdx.x;
    int lane = tid & 31, warp = tid >> 5;
    int m0 = (warp & 1) * 16;
    int n0w = (warp >> 1) * 32;
    int nblk = blockIdx.x * TN;

    int cchunks = K / TKC;
    int c0 = (int)(((long long)cchunks * blockIdx.y)       / gridDim.y);
    int c1 = (int)(((long long)cchunks * (blockIdx.y + 1)) / gridDim.y);
    int kbeg = c0 * TKC;
    int nchunk = c1 - c0;

    float acc[4][4] = {};

    int am = tid >> 3, ak = (tid & 7) * 4;   // A staging coords (1 seg/thread)
    int gr = lane >> 2, kq = lane & 3;       // fragment coords

    auto prefetch = [&](int chunk) {
        int kb = kbeg + chunk * TKC;
        int s = chunk % NSTAGE;
        cp_async16(&As[s][am][ak], &A[am * K + kb + ak]);
        #pragma unroll
        for (int it = 0; it < 4; ++it) {
            int idx = it * 256 + tid;
            int kk = idx >> 5, c4 = (idx & 31) * 4;
            cp_async16(&Ws[s][kk][c4], &W[(size_t)(kb + kk) * ldW + nblk + c4]);
        }
    };

    #pragma unroll
    for (int c = 0; c < NSTAGE - 1; ++c) {
        if (c < nchunk) prefetch(c);
        cp_commit();
    }

    for (int i = 0; i < nchunk; ++i) {
        cp_wait<NSTAGE - 2>();    // group i complete
        __syncthreads();          // all warps done with compute(i-1) and see stage i
        if (i + NSTAGE - 1 < nchunk) prefetch(i + NSTAGE - 1);
        cp_commit();
        int s = i % NSTAGE;
        #pragma unroll
        for (int ks = 0; ks < 4; ++ks) {
            int k0 = ks * 8;
            unsigned ah[4];
            ah[0] = rna_tf32(As[s][m0 + gr    ][k0 + kq    ]);
            ah[1] = rna_tf32(As[s][m0 + gr + 8][k0 + kq    ]);
            ah[2] = rna_tf32(As[s][m0 + gr    ][k0 + kq + 4]);
            ah[3] = rna_tf32(As[s][m0 + gr + 8][k0 + kq + 4]);
            #pragma unroll
            for (int nt = 0; nt < 4; ++nt) {
                int nb2 = n0w + nt * 8 + gr;
                unsigned bh0 = rna_tf32(Ws[s][k0 + kq    ][nb2]);
                unsigned bh1 = rna_tf32(Ws[s][k0 + kq + 4][nb2]);
                mma_tf32(acc[nt], ah, bh0, bh1);
            }
        }
    }

    int cq = (lane & 3) * 2;
    #pragma unroll
    for (int nt = 0; nt < 4; ++nt) {
        int col = nblk + n0w + nt * 8 + cq;
        atomicAdd(&C[(m0 + gr    ) * Nout + col    ], acc[nt][0]);
        atomicAdd(&C[(m0 + gr    ) * Nout + col + 1], acc[nt][1]);
        atomicAdd(&C[(m0 + gr + 8) * Nout + col    ], acc[nt][2]);
        atomicAdd(&C[(m0 + gr + 8) * Nout + col + 1], acc[nt][3]);
    }
}

// ---------------- attention partial: one block per (b,h,page) ----------------
__global__ void __launch_bounds__(256) attn_partial(
    const float* __restrict__ q, const float* __restrict__ kv,
    const int* __restrict__ bt, const int* __restrict__ sl,
    float* __restrict__ pm, float* __restrict__ ps, float* __restrict__ pa)
{
    int b = blockIdx.x, h = blockIdx.y, sp = blockIdx.z;
    int tid = threadIdx.x, lane = tid & 31, w = tid >> 5;
    int pidx = (b * NHEADS + h) * NSPLIT + sp;
    int seq = sl[b];
    int t0 = sp * CHUNK;
    if (t0 >= seq) {
        if (tid == 0) { pm[pidx] = -INFINITY; ps[pidx] = 0.f; }
        return;
    }
    int nt = seq - t0; if (nt > CHUNK) nt = CHUNK;

    __shared__ float qs[HEADD];
    __shared__ float sc[CHUNK];
    __shared__ int   rbs;              // page base (float index, < 2^31)
    __shared__ float sa[2][HEADD];

    if (tid < HEADD) qs[tid] = q[b * HDIM + h * HEADD + tid];
    if (tid == 0)
        rbs = bt[b * MAXBLK + sp] * (PAGE * NHEADS * HEADD) + h * HEADD;
    __syncthreads();
    int rb = rbs;

    const float scale = 0.08838834764831845f;  // 1/sqrt(128)
    float4 qx = reinterpret_cast<const float4*>(qs)[lane];

    // pass 1: scores. 4 tokens/warp/iter (loads clamped to page row 63 — always
    // resident; stores guarded by nt). Interleaved shfl chains pipeline.
    for (int tb = w * 4; tb < nt; tb += 32) {
        int u1 = min(tb + 1, 63), u2 = min(tb + 2, 63), u3 = min(tb + 3, 63);
        const float* base = kv + rb;
        float4 ka = reinterpret_cast<const float4*>(base + tb * (NHEADS * HEADD))[lane];
        float4 kb2 = reinterpret_cast<const float4*>(base + u1 * (NHEADS * HEADD))[lane];
        float4 kc2 = reinterpret_cast<const float4*>(base + u2 * (NHEADS * HEADD))[lane];
        float4 kd2 = reinterpret_cast<const float4*>(base + u3 * (NHEADS * HEADD))[lane];
        float d0 = ka.x  * qx.x + ka.y  * qx.y + ka.z  * qx.z + ka.w  * qx.w;
        float d1 = kb2.x * qx.x + kb2.y * qx.y + kb2.z * qx.z + kb2.w * qx.w;
        float d2 = kc2.x * qx.x + kc2.y * qx.y + kc2.z * qx.z + kc2.w * qx.w;
        float d3 = kd2.x * qx.x + kd2.y * qx.y + kd2.z * qx.z + kd2.w * qx.w;
        #pragma unroll
        for (int o = 16; o; o >>= 1) {
            d0 += __shfl_xor_sync(0xffffffffu, d0, o);
            d1 += __shfl_xor_sync(0xffffffffu, d1, o);
            d2 += __shfl_xor_sync(0xffffffffu, d2, o);
            d3 += __shfl_xor_sync(0xffffffffu, d3, o);
        }
        if (lane == 0) {
            sc[tb] = d0 * scale;
            if (tb + 1 < nt) sc[tb + 1] = d1 * scale;
            if (tb + 2 < nt) sc[tb + 2] = d2 * scale;
            if (tb + 3 < nt) sc[tb + 3] = d3 * scale;
        }
    }
    __syncthreads();

    // softmax stats in ONE warp (nt <= 64 -> 2 values/lane), then one barrier.
    if (w == 0) {
        float v0 = (lane      < nt) ? sc[lane]      : -INFINITY;
        float v1 = (lane + 32 < nt) ? sc[lane + 32] : -INFINITY;
        float m = fmaxf(v0, v1);
        #pragma unroll
        for (int o = 16; o; o >>= 1) m = fmaxf(m, __shfl_xor_sync(0xffffffffu, m, o));
        float e0 = (lane      < nt) ? __expf(v0 - m) : 0.f;
        float e1 = (lane + 32 < nt) ? __expf(v1 - m) : 0.f;
        if (lane      < nt) sc[lane]      = e0;
        if (lane + 32 < nt) sc[lane + 32] = e1;
        float s = e0 + e1;
        #pragma unroll
        for (int o = 16; o; o >>= 1) s += __shfl_xor_sync(0xffffffffu, s, o);
        if (lane == 0) { pm[pidx] = m; ps[pidx] = s; }
    }
    __syncthreads();

    // pass 2: unnormalized weighted V. 2 halves x 4-way unroll.
    int d = tid & 127, half = tid >> 7;
    const float* Vb = kv + (size_t)NUMBLK * PAGE * NHEADS * HEADD;
    float a0 = 0.f, a1 = 0.f, a2 = 0.f, a3 = 0.f;
    int t = half;
    for (; t + 6 < nt; t += 8) {
        const float* v0 = Vb + rb + (t    ) * (NHEADS * HEADD);
        const float* v1 = Vb + rb + (t + 2) * (NHEADS * HEADD);
        const float* v2 = Vb + rb + (t + 4) * (NHEADS * HEADD);
        const float* v3 = Vb + rb + (t + 6) * (NHEADS * HEADD);
        a0 += sc[t    ] * v0[d];
        a1 += sc[t + 2] * v1[d];
        a2 += sc[t + 4] * v2[d];
        a3 += sc[t + 6] * v3[d];
    }
    for (; t < nt; t += 2) {
        const float* vr = Vb + rb + t * (NHEADS * HEADD);
        a0 += sc[t] * vr[d];
    }
    sa[half][d] = (a0 + a1) + (a2 + a3);
    __syncthreads();
    if (tid < HEADD) pa[(size_t)pidx * HEADD + tid] = sa[0][tid] + sa[1][tid];
}

// ---------------- attention combine: one block per (b,h) ----------------
__global__ void __launch_bounds__(128) attn_combine(
    const float* __restrict__ pm, const float* __restrict__ ps,
    const float* __restrict__ pa, float* __restrict__ out)
{
    int b = blockIdx.x, h = blockIdx.y;
    int idx = b * NHEADS + h;
    int tid = threadIdx.x;
    __shared__ float ms[NSPLIT], ss[NSPLIT];
    if (tid < NSPLIT) {
        ms[tid] = pm[idx * NSPLIT + tid];
        ss[tid] = ps[idx * NSPLIT + tid];
    }
    __syncthreads();
    float M = -INFINITY;
    #pragma unroll
    for (int i = 0; i < NSPLIT; i++)
        if (ss[i] > 0.f) M = fmaxf(M, ms[i]);
    float num = 0.f, den = 0.f;
    #pragma unroll
    for (int i = 0; i < NSPLIT; i++) {
        if (ss[i] > 0.f) {
            float wv = __expf(ms[i] - M);
            den += wv * ss[i];
            num += wv * pa[((size_t)idx * NSPLIT + i) * HEADD + tid];
        }
    }
    out[b * HDIM + h * HEADD + tid] = num / den;
}

// ---------------- host launcher ----------------
extern "C" void kernel_launch(void* const* d_in, const int* in_sizes, int n_in,
                              void* d_out, int out_size)
{
    const float* hidden = (const float*)d_in[0];
    const float* kv     = (const float*)d_in[1];
    const int*   bt     = (const int*)d_in[2];
    const int*   sl     = (const int*)d_in[3];
    int p = (n_in > 4 && in_sizes[4] == 1) ? 5 : 4;  // skip max_seq_len if present
    const float* ln1g  = (const float*)d_in[p + 0];
    const float* ln1b  = (const float*)d_in[p + 1];
    const float* ln2g  = (const float*)d_in[p + 2];
    const float* ln2b  = (const float*)d_in[p + 3];
    const float* wattn = (const float*)d_in[p + 4];
    const float* battn = (const float*)d_in[p + 5];
    const float* wproj = (const float*)d_in[p + 6];
    const float* bproj = (const float*)d_in[p + 7];
    const float* wfc   = (const float*)d_in[p + 8];
    const float* bfc   = (const float*)d_in[p + 9];
    const float* wfc2  = (const float*)d_in[p + 10];
    const float* bfc2  = (const float*)d_in[p + 11];
    float* out = (float*)d_out;

    float *x1, *qbuf, *att, *h, *x2, *ffn, *pm, *ps, *pa;
    cudaGetSymbolAddress((void**)&x1,   g_x1);
    cudaGetSymbolAddress((void**)&qbuf, g_q);
    cudaGetSymbolAddress((void**)&att,  g_att);
    cudaGetSymbolAddress((void**)&h,    g_h);
    cudaGetSymbolAddress((void**)&x2,   g_x2);
    cudaGetSymbolAddress((void**)&ffn,  g_ffn);
    cudaGetSymbolAddress((void**)&pm,   g_pm);
    cudaGetSymbolAddress((void**)&ps,   g_ps);
    cudaGetSymbolAddress((void**)&pa,   g_pa);

    cudaFuncSetAttribute(gemm_tc,
        cudaFuncAttributeMaxDynamicSharedMemorySize, GEMM_SMEM);

    // 1. ln1 rows (blocks 0-31) + q/h/ffn bias-inits (rest), one launch
    ln1_init_kernel<<<BATCH + 416, 256>>>(hidden, ln1g, ln1b, x1,
                                          qbuf, battn, h, bproj, ffn, bfc);
    // 2. q = x1 @ w_attn[:, :H] + b_attn[:H]   (16 x 27 = 432 CTAs -> 3/SM)
    gemm_tc<<<dim3(HDIM / TN, 27), 256, GEMM_SMEM>>>(x1, wattn, qbuf, HDIM, HDIM, QKV_N);
    // 3. attention (flash-decode, 32-way page split)
    attn_partial<<<dim3(BATCH, NHEADS, NSPLIT), 256>>>(qbuf, kv, bt, sl, pm, ps, pa);
    attn_combine<<<dim3(BATCH, NHEADS), 128>>>(pm, ps, pa, att);
    // 4. h += attn @ w_proj   (16 x 27 = 432 CTAs)
    gemm_tc<<<dim3(HDIM / TN, 27), 256, GEMM_SMEM>>>(att, wproj, h, HDIM, HDIM, HDIM);
    // 5. ln2 rows + out = h + b_fc2, one launch
    ln2_init_kernel<<<BATCH + 128, 256>>>(h, ln2g, ln2b, x2, out, bfc2);
    // 6. ffn += x2 @ w_fc   (64 x 7 = 448 CTAs)
    gemm_tc<<<dim3(DFF / TN, 7), 256, GEMM_SMEM>>>(x2, wfc, ffn, HDIM, DFF, DFF);
    // 6b. gelu(ffn) in place
    gelu_kernel<<<(BATCH * DFF / 4 + 255) / 256, 256>>>(ffn, BATCH * DFF / 4);
    // 7. out += gelu(ffn) @ w_fc2   (16 x 27 = 432 CTAs)
    gemm_tc<<<dim3(HDIM / TN, 27), 256, GEMM_SMEM>>>(ffn, wfc2, out, DFF, HDIM, HDIM);
}